// round 4
// baseline (speedup 1.0000x reference)
#include <cuda_runtime.h>
#include <cuda_fp16.h>
#include <cstdint>

// ---------------- problem constants ----------------
#define IN_F   4096
#define OUT_F  11008
#define M_TOT  8192
#define GROUP  128

// ---------------- GEMM tiling ----------------
#define BM 128
#define BN 128
#define BK 64                       // halves per k-stage (128B rows -> SW128 atom)
#define NSTAGES 4
#define MT_TILES (M_TOT / BM)       // 64
#define NT_TILES (OUT_F / BN)       // 86
#define KSTAGES  (IN_F / BK)        // 64

#define TILE_BYTES  (128 * BK * 2)            // 16384 per operand tile
#define STAGE_BYTES (2 * TILE_BYTES)          // 32768
#define SMEM_TOTAL  (NSTAGES * STAGE_BYTES)   // 131072

// ---------------- preprocessed operands (static device scratch) ----------------
__device__ uint4 g_x4[(size_t)M_TOT * IN_F / 8];    // 64 MB
__device__ uint4 g_w4[(size_t)OUT_F * IN_F / 8];    // 86 MB
__device__ int   g_scale_mode;                      // 0=f32, 1=f16, 2=bf16

// ---------------- helpers ----------------
__device__ __forceinline__ uint32_t smem_u32(const void* p) {
    uint32_t a;
    asm("{ .reg .u64 t; cvta.to.shared.u64 t, %1; cvt.u32.u64 %0, t; }" : "=r"(a) : "l"(p));
    return a;
}
__device__ __forceinline__ uint32_t sw128(uint32_t off) {
    return off ^ ((off >> 3) & 0x70);
}
__device__ __forceinline__ void cp_async16(uint32_t dst, const void* src) {
    asm volatile("cp.async.cg.shared.global [%0], [%1], 16;" :: "r"(dst), "l"(src) : "memory");
}
#define CP_COMMIT() asm volatile("cp.async.commit_group;" ::: "memory")
#define CP_WAIT(n)  asm volatile("cp.async.wait_group %0;" :: "n"(n) : "memory")

__device__ __forceinline__ void ldsm_x4(uint32_t* r, uint32_t addr) {
    asm volatile("ldmatrix.sync.aligned.m8n8.x4.shared.b16 {%0,%1,%2,%3}, [%4];"
                 : "=r"(r[0]), "=r"(r[1]), "=r"(r[2]), "=r"(r[3]) : "r"(addr));
}
__device__ __forceinline__ void mma16816(float* c, const uint32_t* a, const uint32_t* b) {
    asm volatile(
        "mma.sync.aligned.m16n8k16.row.col.f32.f16.f16.f32 "
        "{%0,%1,%2,%3}, {%4,%5,%6,%7}, {%8,%9}, {%0,%1,%2,%3};"
        : "+f"(c[0]), "+f"(c[1]), "+f"(c[2]), "+f"(c[3])
        : "r"(a[0]), "r"(a[1]), "r"(a[2]), "r"(a[3]), "r"(b[0]), "r"(b[1]));
}
__device__ __forceinline__ uint32_t h2_as_u32(__half2 h) {
    return *reinterpret_cast<uint32_t*>(&h);
}

// ---------------- scales dtype detection ----------------
// scales ~ uniform[0,1)*0.01 -> true values lie in [0, 0.0101). Classify the
// buffer by which reinterpretation puts (nearly) all samples in that range.
__global__ void detect_scale_kernel(const uint32_t* __restrict__ s) {
    int f32c = 0, f16c = 0, bf16c = 0;
    for (int i = 0; i < 64; i++) {
        uint32_t w = s[i];
        float f = __uint_as_float(w);
        if (f >= 1e-6f && f < 0.0101f) f32c++;
        uint32_t h[2] = { w & 0xFFFFu, w >> 16 };
        for (int j = 0; j < 2; j++) {
            float fv = __half2float(__ushort_as_half((unsigned short)h[j]));
            if (fv >= 1e-6f && fv < 0.0101f) f16c++;
            float bv = __uint_as_float(h[j] << 16);
            if (bv >= 1e-6f && bv < 0.0101f) bf16c++;
        }
    }
    g_scale_mode = (f16c > 100) ? 1 : ((bf16c > 100) ? 2 : 0);
}

// ---------------- prep kernels ----------------
__global__ void prep_x_kernel(const float* __restrict__ x) {
    uint32_t idx = blockIdx.x * blockDim.x + threadIdx.x;     // 4194304 total
    uint32_t m = idx >> 9;
    uint32_t k = (idx & 511u) << 3;
    const float4* s = reinterpret_cast<const float4*>(x + (size_t)m * IN_F + k);
    float4 a = s[0], b = s[1];
    uint32_t u0 = h2_as_u32(__floats2half2_rn(a.x, a.y));
    uint32_t u1 = h2_as_u32(__floats2half2_rn(a.z, a.w));
    uint32_t u2 = h2_as_u32(__floats2half2_rn(b.x, b.y));
    uint32_t u3 = h2_as_u32(__floats2half2_rn(b.z, b.w));
    uint32_t mt = m >> 7, r = m & 127u, ks = k >> 6, c = k & 63u;
    size_t blk = ((size_t)mt * KSTAGES + ks) * TILE_BYTES;
    uint32_t off = sw128(r * 128 + c * 2);
    *reinterpret_cast<uint4*>(reinterpret_cast<char*>(g_x4) + blk + off) =
        make_uint4(u0, u1, u2, u3);
}

__global__ void prep_w_kernel(const int* __restrict__ q, const void* __restrict__ scales) {
    uint32_t idx = blockIdx.x * blockDim.x + threadIdx.x;     // 5636096 total
    uint32_t o = idx >> 9;
    uint32_t k = (idx & 511u) << 3;
    uint32_t sidx = o * (IN_F / GROUP) + (k >> 7);
    int mode = g_scale_mode;
    float sc;
    if (mode == 0)      sc = reinterpret_cast<const float*>(scales)[sidx];
    else if (mode == 1) sc = __half2float(reinterpret_cast<const __half*>(scales)[sidx]);
    else                sc = __uint_as_float(
                             (uint32_t)reinterpret_cast<const unsigned short*>(scales)[sidx] << 16);
    const int4* s = reinterpret_cast<const int4*>(q + (size_t)o * IN_F + k);
    int4 a = s[0], b = s[1];
    uint32_t u0 = h2_as_u32(__floats2half2_rn((float)a.x * sc, (float)a.y * sc));
    uint32_t u1 = h2_as_u32(__floats2half2_rn((float)a.z * sc, (float)a.w * sc));
    uint32_t u2 = h2_as_u32(__floats2half2_rn((float)b.x * sc, (float)b.y * sc));
    uint32_t u3 = h2_as_u32(__floats2half2_rn((float)b.z * sc, (float)b.w * sc));
    uint32_t nt = o >> 7, r = o & 127u, ks = k >> 6, c = k & 63u;
    size_t blk = ((size_t)nt * KSTAGES + ks) * TILE_BYTES;
    uint32_t off = sw128(r * 128 + c * 2);
    *reinterpret_cast<uint4*>(reinterpret_cast<char*>(g_w4) + blk + off) =
        make_uint4(u0, u1, u2, u3);
}

// ---------------- GEMM kernel (mma.sync multistage) ----------------
// 256 threads, 8 warps: 2 (M) x 4 (N), warp tile 64x32.

__global__ __launch_bounds__(256, 1)
void gemm_kernel(float* __restrict__ out, const float* __restrict__ bias) {
    extern __shared__ __align__(1024) char smem[];
    uint32_t sb = smem_u32(smem);
    int tid = threadIdx.x;
    int lane = tid & 31, wid = tid >> 5;
    int warp_m = wid & 1, warp_n = wid >> 1;
    int nt = blockIdx.x, mt = blockIdx.y;

    const char* asrc = reinterpret_cast<const char*>(g_x4) + (size_t)mt * KSTAGES * TILE_BYTES;
    const char* bsrc = reinterpret_cast<const char*>(g_w4) + (size_t)nt * KSTAGES * TILE_BYTES;

    auto copy_stage = [&](int s, int ks) {
        uint32_t dstbase = sb + s * STAGE_BYTES;
        if (tid < 128) {
            const char* src = asrc + (size_t)ks * TILE_BYTES + tid * 16;
            uint32_t dst = dstbase + tid * 16;
            #pragma unroll
            for (int j = 0; j < 8; j++) cp_async16(dst + j * 2048, src + j * 2048);
        } else {
            int t = tid - 128;
            const char* src = bsrc + (size_t)ks * TILE_BYTES + t * 16;
            uint32_t dst = dstbase + TILE_BYTES + t * 16;
            #pragma unroll
            for (int j = 0; j < 8; j++) cp_async16(dst + j * 2048, src + j * 2048);
        }
    };

    float acc[4][4][4];
    #pragma unroll
    for (int i = 0; i < 4; i++)
        #pragma unroll
        for (int j = 0; j < 4; j++)
            #pragma unroll
            for (int v = 0; v < 4; v++) acc[i][j][v] = 0.0f;

    #pragma unroll
    for (int s = 0; s < NSTAGES - 1; s++) {
        copy_stage(s, s);
        CP_COMMIT();
    }

    for (int ks = 0; ks < KSTAGES; ks++) {
        CP_WAIT(NSTAGES - 2);
        __syncthreads();

        int s = ks & (NSTAGES - 1);
        int ksn = ks + NSTAGES - 1;
        if (ksn < KSTAGES) copy_stage(ksn & (NSTAGES - 1), ksn);
        CP_COMMIT();

        uint32_t Ab = sb + s * STAGE_BYTES;
        uint32_t Bb = Ab + TILE_BYTES;

        #pragma unroll
        for (int kk = 0; kk < 4; kk++) {            // 4 x k16 per stage
            uint32_t ra[4][4];
            uint32_t rb[4][2];
            #pragma unroll
            for (int im = 0; im < 4; im++) {        // A: 4 m-tiles of 16
                int row = warp_m * 64 + im * 16 + (lane & 15);
                int kb  = kk * 32 + ((lane >> 4) << 4);     // bytes
                ldsm_x4(ra[im], Ab + sw128((uint32_t)(row * 128 + kb)));
            }
            #pragma unroll
            for (int ib = 0; ib < 2; ib++) {        // B: 2 x ldmatrix.x4 -> 4 n-tiles of 8
                int grp  = lane >> 3;
                int nrow = warp_n * 32 + ib * 16 + ((grp >> 1) << 3) + (lane & 7);
                int kb   = kk * 32 + ((grp & 1) << 4);      // bytes
                uint32_t r4[4];
                ldsm_x4(r4, Bb + sw128((uint32_t)(nrow * 128 + kb)));
                rb[ib * 2 + 0][0] = r4[0]; rb[ib * 2 + 0][1] = r4[1];
                rb[ib * 2 + 1][0] = r4[2]; rb[ib * 2 + 1][1] = r4[3];
            }
            #pragma unroll
            for (int im = 0; im < 4; im++)
                #pragma unroll
                for (int in = 0; in < 4; in++)
                    mma16816(acc[im][in], ra[im], rb[in]);
        }
    }

    // ---- epilogue: add bias, store float2 per c-frag pair ----
    #pragma unroll
    for (int im = 0; im < 4; im++) {
        int row = mt * BM + warp_m * 64 + im * 16 + (lane >> 2);
        #pragma unroll
        for (int in = 0; in < 4; in++) {
            int col = nt * BN + warp_n * 32 + in * 8 + ((lane & 3) << 1);
            float2 bv = *reinterpret_cast<const float2*>(bias + col);
            float2 v0 = make_float2(acc[im][in][0] + bv.x, acc[im][in][1] + bv.y);
            float2 v1 = make_float2(acc[im][in][2] + bv.x, acc[im][in][3] + bv.y);
            *reinterpret_cast<float2*>(out + (size_t)row * OUT_F + col) = v0;
            *reinterpret_cast<float2*>(out + (size_t)(row + 8) * OUT_F + col) = v1;
        }
    }
}

// ---------------- launch ----------------
extern "C" void kernel_launch(void* const* d_in, const int* in_sizes, int n_in,
                              void* d_out, int out_size) {
    // Bind inputs by element count (robust to ordering):
    //   x: 33554432 (f32), weight_q: 45088768 (i32), scales: 352256, bias: 11008 (f32)
    const float* x    = nullptr;
    const int*   wq   = nullptr;
    const void*  sc   = nullptr;
    const float* bias = nullptr;
    for (int i = 0; i < n_in; i++) {
        long n = in_sizes[i];
        if      (n == (long)M_TOT * IN_F)           x    = (const float*)d_in[i];
        else if (n == (long)OUT_F * IN_F)           wq   = (const int*)d_in[i];
        else if (n == (long)OUT_F * (IN_F / GROUP)) sc   = d_in[i];
        else if (n == (long)OUT_F)                  bias = (const float*)d_in[i];
    }
    float* out = (float*)d_out;

    cudaFuncSetAttribute(gemm_kernel, cudaFuncAttributeMaxDynamicSharedMemorySize, SMEM_TOTAL);

    detect_scale_kernel<<<1, 1>>>((const uint32_t*)sc);
    prep_x_kernel<<<(M_TOT * IN_F / 8) / 256, 256>>>(x);
    prep_w_kernel<<<(OUT_F * IN_F / 8) / 256, 256>>>(wq, sc);

    dim3 grid(NT_TILES, MT_TILES);   // nt fastest -> wave keeps W resident in L2
    gemm_kernel<<<grid, 256, SMEM_TOTAL>>>(out, bias);
}

// round 5
// speedup vs baseline: 1.2634x; 1.2634x over previous
#include <cuda_runtime.h>
#include <cuda_fp16.h>
#include <cstdint>

// ---------------- problem constants ----------------
#define IN_F   4096
#define OUT_F  11008
#define M_TOT  8192
#define GROUP  128

// ---------------- GEMM tiling ----------------
#define BM 128
#define BN 128
#define BK 64                       // halves per k-stage (128B rows -> SW128 atom)
#define NSTAGES 3
#define MT_TILES (M_TOT / BM)       // 64
#define NT_TILES (OUT_F / BN)       // 86
#define KSTAGES  (IN_F / BK)        // 64

#define TILE_BYTES  (128 * BK * 2)            // 16384 per operand tile
#define STAGE_BYTES (2 * TILE_BYTES)          // 32768
#define SMEM_TOTAL  (NSTAGES * STAGE_BYTES)   // 98304 -> 2 CTAs/SM

// ---------------- preprocessed operands (static device scratch) ----------------
__device__ uint4 g_x4[(size_t)M_TOT * IN_F / 8];    // 64 MB
__device__ uint4 g_w4[(size_t)OUT_F * IN_F / 8];    // 86 MB
__device__ int   g_scale_mode;                      // 0=f32, 1=f16, 2=bf16

// ---------------- helpers ----------------
__device__ __forceinline__ uint32_t smem_u32(const void* p) {
    uint32_t a;
    asm("{ .reg .u64 t; cvta.to.shared.u64 t, %1; cvt.u32.u64 %0, t; }" : "=r"(a) : "l"(p));
    return a;
}
__device__ __forceinline__ uint32_t sw128(uint32_t off) {
    return off ^ ((off >> 3) & 0x70);
}
__device__ __forceinline__ void cp_async16(uint32_t dst, const void* src) {
    asm volatile("cp.async.cg.shared.global [%0], [%1], 16;" :: "r"(dst), "l"(src) : "memory");
}
#define CP_COMMIT() asm volatile("cp.async.commit_group;" ::: "memory")
#define CP_WAIT(n)  asm volatile("cp.async.wait_group %0;" :: "n"(n) : "memory")

__device__ __forceinline__ void ldsm_x4(uint32_t* r, uint32_t addr) {
    asm volatile("ldmatrix.sync.aligned.m8n8.x4.shared.b16 {%0,%1,%2,%3}, [%4];"
                 : "=r"(r[0]), "=r"(r[1]), "=r"(r[2]), "=r"(r[3]) : "r"(addr));
}
__device__ __forceinline__ void mma16816(float* c, const uint32_t* a, const uint32_t* b) {
    asm volatile(
        "mma.sync.aligned.m16n8k16.row.col.f32.f16.f16.f32 "
        "{%0,%1,%2,%3}, {%4,%5,%6,%7}, {%8,%9}, {%0,%1,%2,%3};"
        : "+f"(c[0]), "+f"(c[1]), "+f"(c[2]), "+f"(c[3])
        : "r"(a[0]), "r"(a[1]), "r"(a[2]), "r"(a[3]), "r"(b[0]), "r"(b[1]));
}
__device__ __forceinline__ uint32_t h2_as_u32(__half2 h) {
    return *reinterpret_cast<uint32_t*>(&h);
}

// ---------------- scales dtype detection ----------------
__global__ void detect_scale_kernel(const uint32_t* __restrict__ s) {
    int f32c = 0, f16c = 0, bf16c = 0;
    for (int i = 0; i < 64; i++) {
        uint32_t w = s[i];
        float f = __uint_as_float(w);
        if (f >= 1e-6f && f < 0.0101f) f32c++;
        uint32_t h[2] = { w & 0xFFFFu, w >> 16 };
        for (int j = 0; j < 2; j++) {
            float fv = __half2float(__ushort_as_half((unsigned short)h[j]));
            if (fv >= 1e-6f && fv < 0.0101f) f16c++;
            float bv = __uint_as_float(h[j] << 16);
            if (bv >= 1e-6f && bv < 0.0101f) bf16c++;
        }
    }
    g_scale_mode = (f16c > 100) ? 1 : ((bf16c > 100) ? 2 : 0);
}

// ---------------- prep kernels ----------------
__global__ void prep_x_kernel(const float* __restrict__ x) {
    uint32_t idx = blockIdx.x * blockDim.x + threadIdx.x;     // 4194304 total
    uint32_t m = idx >> 9;
    uint32_t k = (idx & 511u) << 3;
    const float4* s = reinterpret_cast<const float4*>(x + (size_t)m * IN_F + k);
    float4 a = s[0], b = s[1];
    uint32_t u0 = h2_as_u32(__floats2half2_rn(a.x, a.y));
    uint32_t u1 = h2_as_u32(__floats2half2_rn(a.z, a.w));
    uint32_t u2 = h2_as_u32(__floats2half2_rn(b.x, b.y));
    uint32_t u3 = h2_as_u32(__floats2half2_rn(b.z, b.w));
    uint32_t mt = m >> 7, r = m & 127u, ks = k >> 6, c = k & 63u;
    size_t blk = ((size_t)mt * KSTAGES + ks) * TILE_BYTES;
    uint32_t off = sw128(r * 128 + c * 2);
    *reinterpret_cast<uint4*>(reinterpret_cast<char*>(g_x4) + blk + off) =
        make_uint4(u0, u1, u2, u3);
}

__global__ void prep_w_kernel(const int* __restrict__ q, const void* __restrict__ scales) {
    uint32_t idx = blockIdx.x * blockDim.x + threadIdx.x;     // 5636096 total
    uint32_t o = idx >> 9;
    uint32_t k = (idx & 511u) << 3;
    uint32_t sidx = o * (IN_F / GROUP) + (k >> 7);
    int mode = g_scale_mode;
    float sc;
    if (mode == 0)      sc = reinterpret_cast<const float*>(scales)[sidx];
    else if (mode == 1) sc = __half2float(reinterpret_cast<const __half*>(scales)[sidx]);
    else                sc = __uint_as_float(
                             (uint32_t)reinterpret_cast<const unsigned short*>(scales)[sidx] << 16);
    const int4* s = reinterpret_cast<const int4*>(q + (size_t)o * IN_F + k);
    int4 a = s[0], b = s[1];
    uint32_t u0 = h2_as_u32(__floats2half2_rn((float)a.x * sc, (float)a.y * sc));
    uint32_t u1 = h2_as_u32(__floats2half2_rn((float)a.z * sc, (float)a.w * sc));
    uint32_t u2 = h2_as_u32(__floats2half2_rn((float)b.x * sc, (float)b.y * sc));
    uint32_t u3 = h2_as_u32(__floats2half2_rn((float)b.z * sc, (float)b.w * sc));
    uint32_t nt = o >> 7, r = o & 127u, ks = k >> 6, c = k & 63u;
    size_t blk = ((size_t)nt * KSTAGES + ks) * TILE_BYTES;
    uint32_t off = sw128(r * 128 + c * 2);
    *reinterpret_cast<uint4*>(reinterpret_cast<char*>(g_w4) + blk + off) =
        make_uint4(u0, u1, u2, u3);
}

// ---------------- GEMM kernel (mma.sync multistage) ----------------
// 256 threads, 8 warps: 2 (M) x 4 (N), warp tile 64x32. 2 CTAs/SM.

__global__ __launch_bounds__(256, 2)
void gemm_kernel(float* __restrict__ out, const float* __restrict__ bias) {
    extern __shared__ __align__(1024) char smem[];
    uint32_t sb = smem_u32(smem);
    int tid = threadIdx.x;
    int lane = tid & 31, wid = tid >> 5;
    int warp_m = wid & 1, warp_n = wid >> 1;
    int nt = blockIdx.x, mt = blockIdx.y;

    const char* asrc = reinterpret_cast<const char*>(g_x4) + (size_t)mt * KSTAGES * TILE_BYTES;
    const char* bsrc = reinterpret_cast<const char*>(g_w4) + (size_t)nt * KSTAGES * TILE_BYTES;

    auto copy_stage = [&](int s, int ks) {
        uint32_t dstbase = sb + s * STAGE_BYTES;
        if (tid < 128) {
            const char* src = asrc + (size_t)ks * TILE_BYTES + tid * 16;
            uint32_t dst = dstbase + tid * 16;
            #pragma unroll
            for (int j = 0; j < 8; j++) cp_async16(dst + j * 2048, src + j * 2048);
        } else {
            int t = tid - 128;
            const char* src = bsrc + (size_t)ks * TILE_BYTES + t * 16;
            uint32_t dst = dstbase + TILE_BYTES + t * 16;
            #pragma unroll
            for (int j = 0; j < 8; j++) cp_async16(dst + j * 2048, src + j * 2048);
        }
    };

    float acc[4][4][4];
    #pragma unroll
    for (int i = 0; i < 4; i++)
        #pragma unroll
        for (int j = 0; j < 4; j++)
            #pragma unroll
            for (int v = 0; v < 4; v++) acc[i][j][v] = 0.0f;

    // prologue: fill NSTAGES-1 = 2 stages
    copy_stage(0, 0); CP_COMMIT();
    copy_stage(1, 1); CP_COMMIT();

    int scomp = 0;                 // stage to compute this iteration
    int sfill = NSTAGES - 1;       // stage slot to fill with ks+2
    for (int ks = 0; ks < KSTAGES; ks++) {
        CP_WAIT(NSTAGES - 2);
        __syncthreads();

        int ksn = ks + NSTAGES - 1;
        if (ksn < KSTAGES) copy_stage(sfill, ksn);
        CP_COMMIT();
        if (++sfill == NSTAGES) sfill = 0;

        uint32_t Ab = sb + scomp * STAGE_BYTES;
        uint32_t Bb = Ab + TILE_BYTES;
        if (++scomp == NSTAGES) scomp = 0;

        #pragma unroll
        for (int kk = 0; kk < 4; kk++) {            // 4 x k16 per stage
            uint32_t ra[4][4];
            uint32_t rb[4][2];
            #pragma unroll
            for (int im = 0; im < 4; im++) {        // A: 4 m-tiles of 16
                int row = warp_m * 64 + im * 16 + (lane & 15);
                int kb  = kk * 32 + ((lane >> 4) << 4);     // bytes
                ldsm_x4(ra[im], Ab + sw128((uint32_t)(row * 128 + kb)));
            }
            #pragma unroll
            for (int ib = 0; ib < 2; ib++) {        // B: 2 x ldmatrix.x4 -> 4 n-tiles of 8
                int grp  = lane >> 3;
                int nrow = warp_n * 32 + ib * 16 + ((grp >> 1) << 3) + (lane & 7);
                int kb   = kk * 32 + ((grp & 1) << 4);      // bytes
                uint32_t r4[4];
                ldsm_x4(r4, Bb + sw128((uint32_t)(nrow * 128 + kb)));
                rb[ib * 2 + 0][0] = r4[0]; rb[ib * 2 + 0][1] = r4[1];
                rb[ib * 2 + 1][0] = r4[2]; rb[ib * 2 + 1][1] = r4[3];
            }
            #pragma unroll
            for (int im = 0; im < 4; im++)
                #pragma unroll
                for (int in = 0; in < 4; in++)
                    mma16816(acc[im][in], ra[im], rb[in]);
        }
    }

    // ---- epilogue: add bias, store float2 per c-frag pair ----
    #pragma unroll
    for (int im = 0; im < 4; im++) {
        int row = mt * BM + warp_m * 64 + im * 16 + (lane >> 2);
        #pragma unroll
        for (int in = 0; in < 4; in++) {
            int col = nt * BN + warp_n * 32 + in * 8 + ((lane & 3) << 1);
            float2 bv = *reinterpret_cast<const float2*>(bias + col);
            float2 v0 = make_float2(acc[im][in][0] + bv.x, acc[im][in][1] + bv.y);
            float2 v1 = make_float2(acc[im][in][2] + bv.x, acc[im][in][3] + bv.y);
            *reinterpret_cast<float2*>(out + (size_t)row * OUT_F + col) = v0;
            *reinterpret_cast<float2*>(out + (size_t)(row + 8) * OUT_F + col) = v1;
        }
    }
}

// ---------------- launch ----------------
extern "C" void kernel_launch(void* const* d_in, const int* in_sizes, int n_in,
                              void* d_out, int out_size) {
    const float* x    = nullptr;
    const int*   wq   = nullptr;
    const void*  sc   = nullptr;
    const float* bias = nullptr;
    for (int i = 0; i < n_in; i++) {
        long n = in_sizes[i];
        if      (n == (long)M_TOT * IN_F)           x    = (const float*)d_in[i];
        else if (n == (long)OUT_F * IN_F)           wq   = (const int*)d_in[i];
        else if (n == (long)OUT_F * (IN_F / GROUP)) sc   = d_in[i];
        else if (n == (long)OUT_F)                  bias = (const float*)d_in[i];
    }
    float* out = (float*)d_out;

    cudaFuncSetAttribute(gemm_kernel, cudaFuncAttributeMaxDynamicSharedMemorySize, SMEM_TOTAL);

    detect_scale_kernel<<<1, 1>>>((const uint32_t*)sc);
    prep_x_kernel<<<(M_TOT * IN_F / 8) / 256, 256>>>(x);
    prep_w_kernel<<<(OUT_F * IN_F / 8) / 256, 256>>>(wq, sc);

    dim3 grid(NT_TILES, MT_TILES);   // nt fastest -> wave keeps W resident in L2
    gemm_kernel<<<grid, 256, SMEM_TOTAL>>>(out, bias);
}

// round 6
// speedup vs baseline: 1.3025x; 1.0309x over previous
#include <cuda_runtime.h>
#include <cuda_fp16.h>
#include <cstdint>

// ---------------- problem constants ----------------
#define IN_F   4096
#define OUT_F  11008
#define M_TOT  8192
#define GROUP  128

// ---------------- GEMM tiling ----------------
#define BM 128
#define BN 128
#define BK 64                       // halves per k-stage (128B rows -> SW128 atom)
#define NSTAGES 3
#define MT_TILES (M_TOT / BM)       // 64
#define NT_TILES (OUT_F / BN)       // 86
#define KSTAGES  (IN_F / BK)        // 64

#define TILE_BYTES  (128 * BK * 2)            // 16384 per operand tile
#define STAGE_BYTES (2 * TILE_BYTES)          // 32768
#define SMEM_TOTAL  (NSTAGES * STAGE_BYTES)   // 98304 -> 2 CTAs/SM

// ---------------- preprocessed operands (static device scratch) ----------------
__device__ uint4 g_x4[(size_t)M_TOT * IN_F / 8];    // 64 MB
__device__ uint4 g_w4[(size_t)OUT_F * IN_F / 8];    // 86 MB
__device__ int   g_scale_mode;                      // 0=f32, 1=f16, 2=bf16

// ---------------- helpers ----------------
__device__ __forceinline__ uint32_t smem_u32(const void* p) {
    uint32_t a;
    asm("{ .reg .u64 t; cvta.to.shared.u64 t, %1; cvt.u32.u64 %0, t; }" : "=r"(a) : "l"(p));
    return a;
}
__device__ __forceinline__ uint32_t sw128(uint32_t off) {
    return off ^ ((off >> 3) & 0x70);
}
__device__ __forceinline__ void cp_async16(uint32_t dst, const void* src) {
    asm volatile("cp.async.cg.shared.global [%0], [%1], 16;" :: "r"(dst), "l"(src) : "memory");
}
#define CP_COMMIT() asm volatile("cp.async.commit_group;" ::: "memory")
#define CP_WAIT(n)  asm volatile("cp.async.wait_group %0;" :: "n"(n) : "memory")

__device__ __forceinline__ void ldsm_x4(uint32_t* r, uint32_t addr) {
    asm volatile("ldmatrix.sync.aligned.m8n8.x4.shared.b16 {%0,%1,%2,%3}, [%4];"
                 : "=r"(r[0]), "=r"(r[1]), "=r"(r[2]), "=r"(r[3]) : "r"(addr));
}
__device__ __forceinline__ void mma16816(float* c, const uint32_t* a, const uint32_t* b) {
    asm volatile(
        "mma.sync.aligned.m16n8k16.row.col.f32.f16.f16.f32 "
        "{%0,%1,%2,%3}, {%4,%5,%6,%7}, {%8,%9}, {%0,%1,%2,%3};"
        : "+f"(c[0]), "+f"(c[1]), "+f"(c[2]), "+f"(c[3])
        : "r"(a[0]), "r"(a[1]), "r"(a[2]), "r"(a[3]), "r"(b[0]), "r"(b[1]));
}
__device__ __forceinline__ uint32_t h2_as_u32(__half2 h) {
    return *reinterpret_cast<uint32_t*>(&h);
}

// ---------------- scales dtype detection ----------------
__global__ void detect_scale_kernel(const uint32_t* __restrict__ s) {
    int f32c = 0, f16c = 0, bf16c = 0;
    for (int i = 0; i < 64; i++) {
        uint32_t w = s[i];
        float f = __uint_as_float(w);
        if (f >= 1e-6f && f < 0.0101f) f32c++;
        uint32_t h[2] = { w & 0xFFFFu, w >> 16 };
        for (int j = 0; j < 2; j++) {
            float fv = __half2float(__ushort_as_half((unsigned short)h[j]));
            if (fv >= 1e-6f && fv < 0.0101f) f16c++;
            float bv = __uint_as_float(h[j] << 16);
            if (bv >= 1e-6f && bv < 0.0101f) bf16c++;
        }
    }
    g_scale_mode = (f16c > 100) ? 1 : ((bf16c > 100) ? 2 : 0);
}

// ---------------- prep kernels ----------------
__global__ void prep_x_kernel(const float* __restrict__ x) {
    uint32_t idx = blockIdx.x * blockDim.x + threadIdx.x;     // 4194304 total
    uint32_t m = idx >> 9;
    uint32_t k = (idx & 511u) << 3;
    const float4* s = reinterpret_cast<const float4*>(x + (size_t)m * IN_F + k);
    float4 a = s[0], b = s[1];
    uint32_t u0 = h2_as_u32(__floats2half2_rn(a.x, a.y));
    uint32_t u1 = h2_as_u32(__floats2half2_rn(a.z, a.w));
    uint32_t u2 = h2_as_u32(__floats2half2_rn(b.x, b.y));
    uint32_t u3 = h2_as_u32(__floats2half2_rn(b.z, b.w));
    uint32_t mt = m >> 7, r = m & 127u, ks = k >> 6, c = k & 63u;
    size_t blk = ((size_t)mt * KSTAGES + ks) * TILE_BYTES;
    uint32_t off = sw128(r * 128 + c * 2);
    *reinterpret_cast<uint4*>(reinterpret_cast<char*>(g_x4) + blk + off) =
        make_uint4(u0, u1, u2, u3);
}

__global__ void prep_w_kernel(const int* __restrict__ q, const void* __restrict__ scales) {
    uint32_t idx = blockIdx.x * blockDim.x + threadIdx.x;     // 5636096 total
    uint32_t o = idx >> 9;
    uint32_t k = (idx & 511u) << 3;
    uint32_t sidx = o * (IN_F / GROUP) + (k >> 7);
    int mode = g_scale_mode;
    float sc;
    if (mode == 0)      sc = reinterpret_cast<const float*>(scales)[sidx];
    else if (mode == 1) sc = __half2float(reinterpret_cast<const __half*>(scales)[sidx]);
    else                sc = __uint_as_float(
                             (uint32_t)reinterpret_cast<const unsigned short*>(scales)[sidx] << 16);
    const int4* s = reinterpret_cast<const int4*>(q + (size_t)o * IN_F + k);
    int4 a = s[0], b = s[1];
    uint32_t u0 = h2_as_u32(__floats2half2_rn((float)a.x * sc, (float)a.y * sc));
    uint32_t u1 = h2_as_u32(__floats2half2_rn((float)a.z * sc, (float)a.w * sc));
    uint32_t u2 = h2_as_u32(__floats2half2_rn((float)b.x * sc, (float)b.y * sc));
    uint32_t u3 = h2_as_u32(__floats2half2_rn((float)b.z * sc, (float)b.w * sc));
    uint32_t nt = o >> 7, r = o & 127u, ks = k >> 6, c = k & 63u;
    size_t blk = ((size_t)nt * KSTAGES + ks) * TILE_BYTES;
    uint32_t off = sw128(r * 128 + c * 2);
    *reinterpret_cast<uint4*>(reinterpret_cast<char*>(g_w4) + blk + off) =
        make_uint4(u0, u1, u2, u3);
}

// ---------------- GEMM kernel (mma.sync multistage) ----------------
// 256 threads, 8 warps: 2 (M) x 4 (N), warp tile 64x32. 2 CTAs/SM.

__global__ __launch_bounds__(256, 2)
void gemm_kernel(float* __restrict__ out, const float* __restrict__ bias) {
    extern __shared__ __align__(1024) char smem[];
    uint32_t sb = smem_u32(smem);
    int tid = threadIdx.x;
    int lane = tid & 31, wid = tid >> 5;
    int warp_m = wid & 1, warp_n = wid >> 1;
    int nt = blockIdx.x, mt = blockIdx.y;

    const char* asrc = reinterpret_cast<const char*>(g_x4) + (size_t)mt * KSTAGES * TILE_BYTES;
    const char* bsrc = reinterpret_cast<const char*>(g_w4) + (size_t)nt * KSTAGES * TILE_BYTES;

    auto copy_stage = [&](int s, int ks) {
        uint32_t dstbase = sb + s * STAGE_BYTES;
        if (tid < 128) {
            const char* src = asrc + (size_t)ks * TILE_BYTES + tid * 16;
            uint32_t dst = dstbase + tid * 16;
            #pragma unroll
            for (int j = 0; j < 8; j++) cp_async16(dst + j * 2048, src + j * 2048);
        } else {
            int t = tid - 128;
            const char* src = bsrc + (size_t)ks * TILE_BYTES + t * 16;
            uint32_t dst = dstbase + TILE_BYTES + t * 16;
            #pragma unroll
            for (int j = 0; j < 8; j++) cp_async16(dst + j * 2048, src + j * 2048);
        }
    };

    float acc[4][4][4];
    #pragma unroll
    for (int i = 0; i < 4; i++)
        #pragma unroll
        for (int j = 0; j < 4; j++)
            #pragma unroll
            for (int v = 0; v < 4; v++) acc[i][j][v] = 0.0f;

    // Precomputed per-lane ldmatrix address components (bytes within tile)
    int a_row  = warp_m * 64 + (lane & 15);          // + im*16
    int a_kb   = (lane >> 4) << 4;                    // + kk*32
    int grp    = lane >> 3;
    int b_nrow = warp_n * 32 + ((grp >> 1) << 3) + (lane & 7);   // + ib*16
    int b_kb   = (grp & 1) << 4;                      // + kk*32

    // One k16x2 step: interleaved ldmatrix/mma (volatile asm fixes issue order)
    auto do_kk = [&](uint32_t Ab, uint32_t Bb, int kk) {
        uint32_t ra[4][4];
        uint32_t rb[4][2];
        int kbA = kk * 32 + a_kb;
        int kbB = kk * 32 + b_kb;
        // A rows 0,1 and both B tiles first
        ldsm_x4(ra[0], Ab + sw128((uint32_t)((a_row +  0) * 128 + kbA)));
        ldsm_x4(ra[1], Ab + sw128((uint32_t)((a_row + 16) * 128 + kbA)));
        {
            uint32_t r4[4];
            ldsm_x4(r4, Bb + sw128((uint32_t)((b_nrow + 0) * 128 + kbB)));
            rb[0][0] = r4[0]; rb[0][1] = r4[1];
            rb[1][0] = r4[2]; rb[1][1] = r4[3];
            ldsm_x4(r4, Bb + sw128((uint32_t)((b_nrow + 16) * 128 + kbB)));
            rb[2][0] = r4[0]; rb[2][1] = r4[1];
            rb[3][0] = r4[2]; rb[3][1] = r4[3];
        }
        // mma row0 covers latency of A2; row1 covers A3
        #pragma unroll
        for (int in = 0; in < 4; in++) mma16816(acc[0][in], ra[0], rb[in]);
        ldsm_x4(ra[2], Ab + sw128((uint32_t)((a_row + 32) * 128 + kbA)));
        #pragma unroll
        for (int in = 0; in < 4; in++) mma16816(acc[1][in], ra[1], rb[in]);
        ldsm_x4(ra[3], Ab + sw128((uint32_t)((a_row + 48) * 128 + kbA)));
        #pragma unroll
        for (int in = 0; in < 4; in++) mma16816(acc[2][in], ra[2], rb[in]);
        #pragma unroll
        for (int in = 0; in < 4; in++) mma16816(acc[3][in], ra[3], rb[in]);
    };

    // prologue: fill NSTAGES-1 = 2 stages
    copy_stage(0, 0); CP_COMMIT();
    copy_stage(1, 1); CP_COMMIT();

    int scomp = 0;                 // stage to compute this iteration
    int sfill = NSTAGES - 1;       // stage slot to fill with ks+2
    for (int ks = 0; ks < KSTAGES; ks++) {
        CP_WAIT(NSTAGES - 2);
        __syncthreads();

        uint32_t Ab = sb + scomp * STAGE_BYTES;
        uint32_t Bb = Ab + TILE_BYTES;
        if (++scomp == NSTAGES) scomp = 0;

        // kk=0 compute first, THEN issue next-stage copies (moves the
        // 16-cp.async issue burst out of the post-sync critical path)
        do_kk(Ab, Bb, 0);

        int ksn = ks + NSTAGES - 1;
        if (ksn < KSTAGES) copy_stage(sfill, ksn);
        CP_COMMIT();
        if (++sfill == NSTAGES) sfill = 0;

        do_kk(Ab, Bb, 1);
        do_kk(Ab, Bb, 2);
        do_kk(Ab, Bb, 3);
    }

    // ---- epilogue: add bias, store float2 per c-frag pair ----
    #pragma unroll
    for (int im = 0; im < 4; im++) {
        int row = mt * BM + warp_m * 64 + im * 16 + (lane >> 2);
        #pragma unroll
        for (int in = 0; in < 4; in++) {
            int col = nt * BN + warp_n * 32 + in * 8 + ((lane & 3) << 1);
            float2 bv = *reinterpret_cast<const float2*>(bias + col);
            float2 v0 = make_float2(acc[im][in][0] + bv.x, acc[im][in][1] + bv.y);
            float2 v1 = make_float2(acc[im][in][2] + bv.x, acc[im][in][3] + bv.y);
            *reinterpret_cast<float2*>(out + (size_t)row * OUT_F + col) = v0;
            *reinterpret_cast<float2*>(out + (size_t)(row + 8) * OUT_F + col) = v1;
        }
    }
}

// ---------------- launch ----------------
extern "C" void kernel_launch(void* const* d_in, const int* in_sizes, int n_in,
                              void* d_out, int out_size) {
    const float* x    = nullptr;
    const int*   wq   = nullptr;
    const void*  sc   = nullptr;
    const float* bias = nullptr;
    for (int i = 0; i < n_in; i++) {
        long n = in_sizes[i];
        if      (n == (long)M_TOT * IN_F)           x    = (const float*)d_in[i];
        else if (n == (long)OUT_F * IN_F)           wq   = (const int*)d_in[i];
        else if (n == (long)OUT_F * (IN_F / GROUP)) sc   = d_in[i];
        else if (n == (long)OUT_F)                  bias = (const float*)d_in[i];
    }
    float* out = (float*)d_out;

    cudaFuncSetAttribute(gemm_kernel, cudaFuncAttributeMaxDynamicSharedMemorySize, SMEM_TOTAL);

    detect_scale_kernel<<<1, 1>>>((const uint32_t*)sc);
    prep_x_kernel<<<(M_TOT * IN_F / 8) / 256, 256>>>(x);
    prep_w_kernel<<<(OUT_F * IN_F / 8) / 256, 256>>>(wq, sc);

    dim3 grid(NT_TILES, MT_TILES);   // nt fastest -> wave keeps W resident in L2
    gemm_kernel<<<grid, 256, SMEM_TOTAL>>>(out, bias);
}

// round 7
// speedup vs baseline: 1.3036x; 1.0009x over previous
#include <cuda_runtime.h>
#include <cuda_fp16.h>
#include <cstdint>

// ---------------- problem constants ----------------
#define IN_F   4096
#define OUT_F  11008
#define M_TOT  8192
#define GROUP  128

// ---------------- GEMM tiling ----------------
#define BM 128
#define BN 128
#define BK 64                       // halves per k-stage (128B rows -> SW128 atom)
#define NSTAGES 3
#define MT_TILES (M_TOT / BM)       // 64
#define NT_TILES (OUT_F / BN)       // 86
#define KSTAGES  (IN_F / BK)        // 64

#define TILE_BYTES  (128 * BK * 2)            // 16384 per operand tile
#define STAGE_BYTES (2 * TILE_BYTES)          // 32768
#define SMEM_TOTAL  (NSTAGES * STAGE_BYTES)   // 98304 -> 2 CTAs/SM

// ---------------- preprocessed operands (static device scratch) ----------------
__device__ uint4 g_x4[(size_t)M_TOT * IN_F / 8];    // 64 MB
__device__ uint4 g_w4[(size_t)OUT_F * IN_F / 8];    // 86 MB
__device__ int   g_scale_mode;                      // 0=f32, 1=f16, 2=bf16

// ---------------- helpers ----------------
__device__ __forceinline__ uint32_t smem_u32(const void* p) {
    uint32_t a;
    asm("{ .reg .u64 t; cvta.to.shared.u64 t, %1; cvt.u32.u64 %0, t; }" : "=r"(a) : "l"(p));
    return a;
}
__device__ __forceinline__ uint32_t sw128(uint32_t off) {
    return off ^ ((off >> 3) & 0x70);
}
__device__ __forceinline__ void cp_async16(uint32_t dst, const void* src) {
    asm volatile("cp.async.cg.shared.global [%0], [%1], 16;" :: "r"(dst), "l"(src) : "memory");
}
#define CP_COMMIT() asm volatile("cp.async.commit_group;" ::: "memory")
#define CP_WAIT(n)  asm volatile("cp.async.wait_group %0;" :: "n"(n) : "memory")

__device__ __forceinline__ void ldsm_x4(uint32_t* r, uint32_t addr) {
    asm volatile("ldmatrix.sync.aligned.m8n8.x4.shared.b16 {%0,%1,%2,%3}, [%4];"
                 : "=r"(r[0]), "=r"(r[1]), "=r"(r[2]), "=r"(r[3]) : "r"(addr));
}
// NOTE: non-volatile — register-only deps, lets ptxas schedule HMMAs freely.
__device__ __forceinline__ void mma16816(float* c, const uint32_t* a, const uint32_t* b) {
    asm("mma.sync.aligned.m16n8k16.row.col.f32.f16.f16.f32 "
        "{%0,%1,%2,%3}, {%4,%5,%6,%7}, {%8,%9}, {%0,%1,%2,%3};"
        : "+f"(c[0]), "+f"(c[1]), "+f"(c[2]), "+f"(c[3])
        : "r"(a[0]), "r"(a[1]), "r"(a[2]), "r"(a[3]), "r"(b[0]), "r"(b[1]));
}
__device__ __forceinline__ uint32_t h2_as_u32(__half2 h) {
    return *reinterpret_cast<uint32_t*>(&h);
}

// ---------------- scales dtype detection (parallel, 64 threads) ----------------
__global__ void detect_scale_kernel(const uint32_t* __restrict__ s) {
    int t = threadIdx.x;                       // 64 threads, one word each
    uint32_t w = s[t];
    float f = __uint_as_float(w);
    int f32ok = (f >= 1e-6f && f < 0.0101f) ? 1 : 0;
    int f16ok = 0, bf16ok = 0;
    uint32_t h[2] = { w & 0xFFFFu, w >> 16 };
    #pragma unroll
    for (int j = 0; j < 2; j++) {
        float fv = __half2float(__ushort_as_half((unsigned short)h[j]));
        if (fv >= 1e-6f && fv < 0.0101f) f16ok++;
        float bv = __uint_as_float(h[j] << 16);
        if (bv >= 1e-6f && bv < 0.0101f) bf16ok++;
    }
    __shared__ int cnt[3];
    if (t < 3) cnt[t] = 0;
    __syncthreads();
    atomicAdd(&cnt[0], f32ok);
    atomicAdd(&cnt[1], f16ok);
    atomicAdd(&cnt[2], bf16ok);
    __syncthreads();
    if (t == 0)
        g_scale_mode = (cnt[1] > 100) ? 1 : ((cnt[2] > 100) ? 2 : 0);
}

// ---------------- prep kernels ----------------
__global__ void prep_x_kernel(const float* __restrict__ x) {
    uint32_t idx = blockIdx.x * blockDim.x + threadIdx.x;     // 4194304 total
    uint32_t m = idx >> 9;
    uint32_t k = (idx & 511u) << 3;
    const float4* s = reinterpret_cast<const float4*>(x + (size_t)m * IN_F + k);
    float4 a = s[0], b = s[1];
    uint32_t u0 = h2_as_u32(__floats2half2_rn(a.x, a.y));
    uint32_t u1 = h2_as_u32(__floats2half2_rn(a.z, a.w));
    uint32_t u2 = h2_as_u32(__floats2half2_rn(b.x, b.y));
    uint32_t u3 = h2_as_u32(__floats2half2_rn(b.z, b.w));
    uint32_t mt = m >> 7, r = m & 127u, ks = k >> 6, c = k & 63u;
    size_t blk = ((size_t)mt * KSTAGES + ks) * TILE_BYTES;
    uint32_t off = sw128(r * 128 + c * 2);
    *reinterpret_cast<uint4*>(reinterpret_cast<char*>(g_x4) + blk + off) =
        make_uint4(u0, u1, u2, u3);
}

__global__ void prep_w_kernel(const int* __restrict__ q, const void* __restrict__ scales) {
    uint32_t idx = blockIdx.x * blockDim.x + threadIdx.x;     // 5636096 total
    uint32_t o = idx >> 9;
    uint32_t k = (idx & 511u) << 3;
    uint32_t sidx = o * (IN_F / GROUP) + (k >> 7);
    int mode = g_scale_mode;
    float sc;
    if (mode == 0)      sc = reinterpret_cast<const float*>(scales)[sidx];
    else if (mode == 1) sc = __half2float(reinterpret_cast<const __half*>(scales)[sidx]);
    else                sc = __uint_as_float(
                             (uint32_t)reinterpret_cast<const unsigned short*>(scales)[sidx] << 16);
    const int4* s = reinterpret_cast<const int4*>(q + (size_t)o * IN_F + k);
    int4 a = s[0], b = s[1];
    uint32_t u0 = h2_as_u32(__floats2half2_rn((float)a.x * sc, (float)a.y * sc));
    uint32_t u1 = h2_as_u32(__floats2half2_rn((float)a.z * sc, (float)a.w * sc));
    uint32_t u2 = h2_as_u32(__floats2half2_rn((float)b.x * sc, (float)b.y * sc));
    uint32_t u3 = h2_as_u32(__floats2half2_rn((float)b.z * sc, (float)b.w * sc));
    uint32_t nt = o >> 7, r = o & 127u, ks = k >> 6, c = k & 63u;
    size_t blk = ((size_t)nt * KSTAGES + ks) * TILE_BYTES;
    uint32_t off = sw128(r * 128 + c * 2);
    *reinterpret_cast<uint4*>(reinterpret_cast<char*>(g_w4) + blk + off) =
        make_uint4(u0, u1, u2, u3);
}

// ---------------- GEMM kernel (mma.sync multistage) ----------------
// 256 threads, 8 warps: 2 (M) x 4 (N), warp tile 64x32. 2 CTAs/SM.

__global__ __launch_bounds__(256, 2)
void gemm_kernel(float* __restrict__ out, const float* __restrict__ bias) {
    extern __shared__ __align__(1024) char smem[];
    uint32_t sb = smem_u32(smem);
    int tid = threadIdx.x;
    int lane = tid & 31, wid = tid >> 5;
    int warp_m = wid & 1, warp_n = wid >> 1;
    int nt = blockIdx.x, mt = blockIdx.y;

    const char* asrc = reinterpret_cast<const char*>(g_x4) + (size_t)mt * KSTAGES * TILE_BYTES;
    const char* bsrc = reinterpret_cast<const char*>(g_w4) + (size_t)nt * KSTAGES * TILE_BYTES;

    auto copy_stage = [&](int s, int ks) {
        uint32_t dstbase = sb + s * STAGE_BYTES;
        if (tid < 128) {
            const char* src = asrc + (size_t)ks * TILE_BYTES + tid * 16;
            uint32_t dst = dstbase + tid * 16;
            #pragma unroll
            for (int j = 0; j < 8; j++) cp_async16(dst + j * 2048, src + j * 2048);
        } else {
            int t = tid - 128;
            const char* src = bsrc + (size_t)ks * TILE_BYTES + t * 16;
            uint32_t dst = dstbase + TILE_BYTES + t * 16;
            #pragma unroll
            for (int j = 0; j < 8; j++) cp_async16(dst + j * 2048, src + j * 2048);
        }
    };

    float acc[4][4][4];
    #pragma unroll
    for (int i = 0; i < 4; i++)
        #pragma unroll
        for (int j = 0; j < 4; j++)
            #pragma unroll
            for (int v = 0; v < 4; v++) acc[i][j][v] = 0.0f;

    // Precomputed per-lane ldmatrix address components (bytes within tile)
    int a_row  = warp_m * 64 + (lane & 15);          // + im*16
    int a_kb   = (lane >> 4) << 4;                    // + kk*32
    int grp    = lane >> 3;
    int b_nrow = warp_n * 32 + ((grp >> 1) << 3) + (lane & 7);   // + ib*16
    int b_kb   = (grp & 1) << 4;                      // + kk*32

    // One k16x2 step: interleaved ldmatrix/mma
    auto do_kk = [&](uint32_t Ab, uint32_t Bb, int kk) {
        uint32_t ra[4][4];
        uint32_t rb[4][2];
        int kbA = kk * 32 + a_kb;
        int kbB = kk * 32 + b_kb;
        ldsm_x4(ra[0], Ab + sw128((uint32_t)((a_row +  0) * 128 + kbA)));
        ldsm_x4(ra[1], Ab + sw128((uint32_t)((a_row + 16) * 128 + kbA)));
        {
            uint32_t r4[4];
            ldsm_x4(r4, Bb + sw128((uint32_t)((b_nrow + 0) * 128 + kbB)));
            rb[0][0] = r4[0]; rb[0][1] = r4[1];
            rb[1][0] = r4[2]; rb[1][1] = r4[3];
            ldsm_x4(r4, Bb + sw128((uint32_t)((b_nrow + 16) * 128 + kbB)));
            rb[2][0] = r4[0]; rb[2][1] = r4[1];
            rb[3][0] = r4[2]; rb[3][1] = r4[3];
        }
        #pragma unroll
        for (int in = 0; in < 4; in++) mma16816(acc[0][in], ra[0], rb[in]);
        ldsm_x4(ra[2], Ab + sw128((uint32_t)((a_row + 32) * 128 + kbA)));
        #pragma unroll
        for (int in = 0; in < 4; in++) mma16816(acc[1][in], ra[1], rb[in]);
        ldsm_x4(ra[3], Ab + sw128((uint32_t)((a_row + 48) * 128 + kbA)));
        #pragma unroll
        for (int in = 0; in < 4; in++) mma16816(acc[2][in], ra[2], rb[in]);
        #pragma unroll
        for (int in = 0; in < 4; in++) mma16816(acc[3][in], ra[3], rb[in]);
    };

    // prologue: fill NSTAGES-1 = 2 stages
    copy_stage(0, 0); CP_COMMIT();
    copy_stage(1, 1); CP_COMMIT();

    int scomp = 0;                 // stage to compute this iteration
    int sfill = NSTAGES - 1;       // stage slot to fill with ks+2
    for (int ks = 0; ks < KSTAGES; ks++) {
        CP_WAIT(NSTAGES - 2);
        __syncthreads();

        uint32_t Ab = sb + scomp * STAGE_BYTES;
        uint32_t Bb = Ab + TILE_BYTES;
        if (++scomp == NSTAGES) scomp = 0;

        do_kk(Ab, Bb, 0);

        int ksn = ks + NSTAGES - 1;
        if (ksn < KSTAGES) copy_stage(sfill, ksn);
        CP_COMMIT();
        if (++sfill == NSTAGES) sfill = 0;

        do_kk(Ab, Bb, 1);
        do_kk(Ab, Bb, 2);
        do_kk(Ab, Bb, 3);
    }

    // ---- epilogue: add bias, store float2 per c-frag pair ----
    #pragma unroll
    for (int im = 0; im < 4; im++) {
        int row = mt * BM + warp_m * 64 + im * 16 + (lane >> 2);
        #pragma unroll
        for (int in = 0; in < 4; in++) {
            int col = nt * BN + warp_n * 32 + in * 8 + ((lane & 3) << 1);
            float2 bv = *reinterpret_cast<const float2*>(bias + col);
            float2 v0 = make_float2(acc[im][in][0] + bv.x, acc[im][in][1] + bv.y);
            float2 v1 = make_float2(acc[im][in][2] + bv.x, acc[im][in][3] + bv.y);
            *reinterpret_cast<float2*>(out + (size_t)row * OUT_F + col) = v0;
            *reinterpret_cast<float2*>(out + (size_t)(row + 8) * OUT_F + col) = v1;
        }
    }
}

// ---------------- launch ----------------
extern "C" void kernel_launch(void* const* d_in, const int* in_sizes, int n_in,
                              void* d_out, int out_size) {
    const float* x    = nullptr;
    const int*   wq   = nullptr;
    const void*  sc   = nullptr;
    const float* bias = nullptr;
    for (int i = 0; i < n_in; i++) {
        long n = in_sizes[i];
        if      (n == (long)M_TOT * IN_F)           x    = (const float*)d_in[i];
        else if (n == (long)OUT_F * IN_F)           wq   = (const int*)d_in[i];
        else if (n == (long)OUT_F * (IN_F / GROUP)) sc   = d_in[i];
        else if (n == (long)OUT_F)                  bias = (const float*)d_in[i];
    }
    float* out = (float*)d_out;

    cudaFuncSetAttribute(gemm_kernel, cudaFuncAttributeMaxDynamicSharedMemorySize, SMEM_TOTAL);

    detect_scale_kernel<<<1, 64>>>((const uint32_t*)sc);
    prep_x_kernel<<<(M_TOT * IN_F / 8) / 256, 256>>>(x);
    prep_w_kernel<<<(OUT_F * IN_F / 8) / 256, 256>>>(wq, sc);

    dim3 grid(NT_TILES, MT_TILES);   // nt fastest -> wave keeps W resident in L2
    gemm_kernel<<<grid, 256, SMEM_TOTAL>>>(out, bias);
}

// round 8
// speedup vs baseline: 1.3039x; 1.0002x over previous
#include <cuda_runtime.h>
#include <cuda_fp16.h>
#include <cstdint>

// ---------------- problem constants ----------------
#define IN_F   4096
#define OUT_F  11008
#define M_TOT  8192
#define GROUP  128

// ---------------- GEMM tiling ----------------
#define BM 128
#define BN 128
#define BK 64                       // halves per k-stage (128B rows -> SW128 atom)
#define NSTAGES 3
#define MT_TILES (M_TOT / BM)       // 64
#define NT_TILES (OUT_F / BN)       // 86
#define KSTAGES  (IN_F / BK)        // 64
#define GN 2                        // nt columns per rasterization group (43 groups)

#define TILE_BYTES  (128 * BK * 2)            // 16384 per operand tile
#define STAGE_BYTES (2 * TILE_BYTES)          // 32768
#define SMEM_TOTAL  (NSTAGES * STAGE_BYTES)   // 98304 -> 2 CTAs/SM

// ---------------- preprocessed operands (static device scratch) ----------------
__device__ uint4 g_x4[(size_t)M_TOT * IN_F / 8];    // 64 MB
__device__ uint4 g_w4[(size_t)OUT_F * IN_F / 8];    // 86 MB
__device__ int   g_scale_mode;                      // 0=f32, 1=f16, 2=bf16

// ---------------- helpers ----------------
__device__ __forceinline__ uint32_t smem_u32(const void* p) {
    uint32_t a;
    asm("{ .reg .u64 t; cvta.to.shared.u64 t, %1; cvt.u32.u64 %0, t; }" : "=r"(a) : "l"(p));
    return a;
}
__device__ __forceinline__ uint32_t sw128(uint32_t off) {
    return off ^ ((off >> 3) & 0x70);
}
__device__ __forceinline__ void cp_async16(uint32_t dst, const void* src) {
    asm volatile("cp.async.cg.shared.global [%0], [%1], 16;" :: "r"(dst), "l"(src) : "memory");
}
#define CP_COMMIT() asm volatile("cp.async.commit_group;" ::: "memory")
#define CP_WAIT(n)  asm volatile("cp.async.wait_group %0;" :: "n"(n) : "memory")

__device__ __forceinline__ void ldsm_x4(uint32_t* r, uint32_t addr) {
    asm volatile("ldmatrix.sync.aligned.m8n8.x4.shared.b16 {%0,%1,%2,%3}, [%4];"
                 : "=r"(r[0]), "=r"(r[1]), "=r"(r[2]), "=r"(r[3]) : "r"(addr));
}
__device__ __forceinline__ void mma16816(float* c, const uint32_t* a, const uint32_t* b) {
    asm("mma.sync.aligned.m16n8k16.row.col.f32.f16.f16.f32 "
        "{%0,%1,%2,%3}, {%4,%5,%6,%7}, {%8,%9}, {%0,%1,%2,%3};"
        : "+f"(c[0]), "+f"(c[1]), "+f"(c[2]), "+f"(c[3])
        : "r"(a[0]), "r"(a[1]), "r"(a[2]), "r"(a[3]), "r"(b[0]), "r"(b[1]));
}
__device__ __forceinline__ uint32_t h2_as_u32(__half2 h) {
    return *reinterpret_cast<uint32_t*>(&h);
}

// ---------------- scales dtype detection (parallel, 64 threads) ----------------
__global__ void detect_scale_kernel(const uint32_t* __restrict__ s) {
    int t = threadIdx.x;
    uint32_t w = s[t];
    float f = __uint_as_float(w);
    int f32ok = (f >= 1e-6f && f < 0.0101f) ? 1 : 0;
    int f16ok = 0, bf16ok = 0;
    uint32_t h[2] = { w & 0xFFFFu, w >> 16 };
    #pragma unroll
    for (int j = 0; j < 2; j++) {
        float fv = __half2float(__ushort_as_half((unsigned short)h[j]));
        if (fv >= 1e-6f && fv < 0.0101f) f16ok++;
        float bv = __uint_as_float(h[j] << 16);
        if (bv >= 1e-6f && bv < 0.0101f) bf16ok++;
    }
    __shared__ int cnt[3];
    if (t < 3) cnt[t] = 0;
    __syncthreads();
    atomicAdd(&cnt[0], f32ok);
    atomicAdd(&cnt[1], f16ok);
    atomicAdd(&cnt[2], bf16ok);
    __syncthreads();
    if (t == 0)
        g_scale_mode = (cnt[1] > 100) ? 1 : ((cnt[2] > 100) ? 2 : 0);
}

// ---------------- prep kernels ----------------
__global__ void prep_x_kernel(const float* __restrict__ x) {
    uint32_t idx = blockIdx.x * blockDim.x + threadIdx.x;     // 4194304 total
    uint32_t m = idx >> 9;
    uint32_t k = (idx & 511u) << 3;
    const float4* s = reinterpret_cast<const float4*>(x + (size_t)m * IN_F + k);
    float4 a = s[0], b = s[1];
    uint32_t u0 = h2_as_u32(__floats2half2_rn(a.x, a.y));
    uint32_t u1 = h2_as_u32(__floats2half2_rn(a.z, a.w));
    uint32_t u2 = h2_as_u32(__floats2half2_rn(b.x, b.y));
    uint32_t u3 = h2_as_u32(__floats2half2_rn(b.z, b.w));
    uint32_t mt = m >> 7, r = m & 127u, ks = k >> 6, c = k & 63u;
    size_t blk = ((size_t)mt * KSTAGES + ks) * TILE_BYTES;
    uint32_t off = sw128(r * 128 + c * 2);
    *reinterpret_cast<uint4*>(reinterpret_cast<char*>(g_x4) + blk + off) =
        make_uint4(u0, u1, u2, u3);
}

__global__ void prep_w_kernel(const int* __restrict__ q, const void* __restrict__ scales) {
    uint32_t idx = blockIdx.x * blockDim.x + threadIdx.x;     // 5636096 total
    uint32_t o = idx >> 9;
    uint32_t k = (idx & 511u) << 3;
    uint32_t sidx = o * (IN_F / GROUP) + (k >> 7);
    int mode = g_scale_mode;
    float sc;
    if (mode == 0)      sc = reinterpret_cast<const float*>(scales)[sidx];
    else if (mode == 1) sc = __half2float(reinterpret_cast<const __half*>(scales)[sidx]);
    else                sc = __uint_as_float(
                             (uint32_t)reinterpret_cast<const unsigned short*>(scales)[sidx] << 16);
    const int4* s = reinterpret_cast<const int4*>(q + (size_t)o * IN_F + k);
    int4 a = s[0], b = s[1];
    uint32_t u0 = h2_as_u32(__floats2half2_rn((float)a.x * sc, (float)a.y * sc));
    uint32_t u1 = h2_as_u32(__floats2half2_rn((float)a.z * sc, (float)a.w * sc));
    uint32_t u2 = h2_as_u32(__floats2half2_rn((float)b.x * sc, (float)b.y * sc));
    uint32_t u3 = h2_as_u32(__floats2half2_rn((float)b.z * sc, (float)b.w * sc));
    uint32_t nt = o >> 7, r = o & 127u, ks = k >> 6, c = k & 63u;
    size_t blk = ((size_t)nt * KSTAGES + ks) * TILE_BYTES;
    uint32_t off = sw128(r * 128 + c * 2);
    *reinterpret_cast<uint4*>(reinterpret_cast<char*>(g_w4) + blk + off) =
        make_uint4(u0, u1, u2, u3);
}

// ---------------- GEMM kernel (mma.sync multistage) ----------------
// 256 threads, 8 warps: 2 (M) x 4 (N), warp tile 64x32. 2 CTAs/SM.
// Rasterization: groups of GN nt-columns x all mt (mt advances fast inside a
// group) -> per-group L2 working set = A(64MB, reused every group) + GN MB of W.

__global__ __launch_bounds__(256, 2)
void gemm_kernel(float* __restrict__ out, const float* __restrict__ bias) {
    extern __shared__ __align__(1024) char smem[];
    uint32_t sb = smem_u32(smem);
    int tid = threadIdx.x;
    int lane = tid & 31, wid = tid >> 5;
    int warp_m = wid & 1, warp_n = wid >> 1;

    int bid = blockIdx.x;
    int group = bid / (GN * MT_TILES);
    int r_in  = bid % (GN * MT_TILES);
    int mt = r_in >> 1;                 // mt fastest (pairs share mt)
    int nt = group * GN + (r_in & 1);

    const char* asrc = reinterpret_cast<const char*>(g_x4) + (size_t)mt * KSTAGES * TILE_BYTES;
    const char* bsrc = reinterpret_cast<const char*>(g_w4) + (size_t)nt * KSTAGES * TILE_BYTES;

    auto copy_stage = [&](int s, int ks) {
        uint32_t dstbase = sb + s * STAGE_BYTES;
        if (tid < 128) {
            const char* src = asrc + (size_t)ks * TILE_BYTES + tid * 16;
            uint32_t dst = dstbase + tid * 16;
            #pragma unroll
            for (int j = 0; j < 8; j++) cp_async16(dst + j * 2048, src + j * 2048);
        } else {
            int t = tid - 128;
            const char* src = bsrc + (size_t)ks * TILE_BYTES + t * 16;
            uint32_t dst = dstbase + TILE_BYTES + t * 16;
            #pragma unroll
            for (int j = 0; j < 8; j++) cp_async16(dst + j * 2048, src + j * 2048);
        }
    };

    float acc[4][4][4];
    #pragma unroll
    for (int i = 0; i < 4; i++)
        #pragma unroll
        for (int j = 0; j < 4; j++)
            #pragma unroll
            for (int v = 0; v < 4; v++) acc[i][j][v] = 0.0f;

    int a_row  = warp_m * 64 + (lane & 15);
    int a_kb   = (lane >> 4) << 4;
    int grp    = lane >> 3;
    int b_nrow = warp_n * 32 + ((grp >> 1) << 3) + (lane & 7);
    int b_kb   = (grp & 1) << 4;

    auto do_kk = [&](uint32_t Ab, uint32_t Bb, int kk) {
        uint32_t ra[4][4];
        uint32_t rb[4][2];
        int kbA = kk * 32 + a_kb;
        int kbB = kk * 32 + b_kb;
        ldsm_x4(ra[0], Ab + sw128((uint32_t)((a_row +  0) * 128 + kbA)));
        ldsm_x4(ra[1], Ab + sw128((uint32_t)((a_row + 16) * 128 + kbA)));
        {
            uint32_t r4[4];
            ldsm_x4(r4, Bb + sw128((uint32_t)((b_nrow + 0) * 128 + kbB)));
            rb[0][0] = r4[0]; rb[0][1] = r4[1];
            rb[1][0] = r4[2]; rb[1][1] = r4[3];
            ldsm_x4(r4, Bb + sw128((uint32_t)((b_nrow + 16) * 128 + kbB)));
            rb[2][0] = r4[0]; rb[2][1] = r4[1];
            rb[3][0] = r4[2]; rb[3][1] = r4[3];
        }
        #pragma unroll
        for (int in = 0; in < 4; in++) mma16816(acc[0][in], ra[0], rb[in]);
        ldsm_x4(ra[2], Ab + sw128((uint32_t)((a_row + 32) * 128 + kbA)));
        #pragma unroll
        for (int in = 0; in < 4; in++) mma16816(acc[1][in], ra[1], rb[in]);
        ldsm_x4(ra[3], Ab + sw128((uint32_t)((a_row + 48) * 128 + kbA)));
        #pragma unroll
        for (int in = 0; in < 4; in++) mma16816(acc[2][in], ra[2], rb[in]);
        #pragma unroll
        for (int in = 0; in < 4; in++) mma16816(acc[3][in], ra[3], rb[in]);
    };

    copy_stage(0, 0); CP_COMMIT();
    copy_stage(1, 1); CP_COMMIT();

    int scomp = 0;
    int sfill = NSTAGES - 1;
    for (int ks = 0; ks < KSTAGES; ks++) {
        CP_WAIT(NSTAGES - 2);
        __syncthreads();

        uint32_t Ab = sb + scomp * STAGE_BYTES;
        uint32_t Bb = Ab + TILE_BYTES;
        if (++scomp == NSTAGES) scomp = 0;

        do_kk(Ab, Bb, 0);

        int ksn = ks + NSTAGES - 1;
        if (ksn < KSTAGES) copy_stage(sfill, ksn);
        CP_COMMIT();
        if (++sfill == NSTAGES) sfill = 0;

        do_kk(Ab, Bb, 1);
        do_kk(Ab, Bb, 2);
        do_kk(Ab, Bb, 3);
    }

    // ---- epilogue: add bias, store float2 per c-frag pair ----
    #pragma unroll
    for (int im = 0; im < 4; im++) {
        int row = mt * BM + warp_m * 64 + im * 16 + (lane >> 2);
        #pragma unroll
        for (int in = 0; in < 4; in++) {
            int col = nt * BN + warp_n * 32 + in * 8 + ((lane & 3) << 1);
            float2 bv = *reinterpret_cast<const float2*>(bias + col);
            float2 v0 = make_float2(acc[im][in][0] + bv.x, acc[im][in][1] + bv.y);
            float2 v1 = make_float2(acc[im][in][2] + bv.x, acc[im][in][3] + bv.y);
            *reinterpret_cast<float2*>(out + (size_t)row * OUT_F + col) = v0;
            *reinterpret_cast<float2*>(out + (size_t)(row + 8) * OUT_F + col) = v1;
        }
    }
}

// ---------------- launch ----------------
extern "C" void kernel_launch(void* const* d_in, const int* in_sizes, int n_in,
                              void* d_out, int out_size) {
    const float* x    = nullptr;
    const int*   wq   = nullptr;
    const void*  sc   = nullptr;
    const float* bias = nullptr;
    for (int i = 0; i < n_in; i++) {
        long n = in_sizes[i];
        if      (n == (long)M_TOT * IN_F)           x    = (const float*)d_in[i];
        else if (n == (long)OUT_F * IN_F)           wq   = (const int*)d_in[i];
        else if (n == (long)OUT_F * (IN_F / GROUP)) sc   = d_in[i];
        else if (n == (long)OUT_F)                  bias = (const float*)d_in[i];
    }
    float* out = (float*)d_out;

    cudaFuncSetAttribute(gemm_kernel, cudaFuncAttributeMaxDynamicSharedMemorySize, SMEM_TOTAL);

    detect_scale_kernel<<<1, 64>>>((const uint32_t*)sc);
    prep_x_kernel<<<(M_TOT * IN_F / 8) / 256, 256>>>(x);
    prep_w_kernel<<<(OUT_F * IN_F / 8) / 256, 256>>>(wq, sc);

    gemm_kernel<<<NT_TILES * MT_TILES, 256, SMEM_TOTAL>>>(out, bias);
}

// round 9
// speedup vs baseline: 1.3398x; 1.0275x over previous
#include <cuda_runtime.h>
#include <cuda_fp16.h>
#include <cstdint>

// ---------------- problem constants ----------------
#define IN_F   4096
#define OUT_F  11008
#define M_TOT  8192
#define GROUP  128

// ---------------- GEMM tiling ----------------
#define BM 128
#define BN 128
#define BK 64                       // halves per k-stage (128B rows -> SW128 atom)
#define NSTAGES 3
#define MT_TILES (M_TOT / BM)       // 64
#define NT_TILES (OUT_F / BN)       // 86
#define KSTAGES  (IN_F / BK)        // 64
#define GN 2                        // nt columns per rasterization group

#define TILE_BYTES  (128 * BK * 2)            // 16384 per operand tile
#define STAGE_BYTES (2 * TILE_BYTES)          // 32768
#define MBAR_OFF    (NSTAGES * STAGE_BYTES)   // 98304
#define SMEM_TOTAL  (MBAR_OFF + 64)           // 98368 -> still 2 CTAs/SM
#define MB_FULL(s)  (MBAR_OFF + (s) * 8)
#define MB_EMPTY(s) (MBAR_OFF + 24 + (s) * 8)

// ---------------- preprocessed operands (static device scratch) ----------------
__device__ uint4 g_x4[(size_t)M_TOT * IN_F / 8];    // 64 MB
__device__ uint4 g_w4[(size_t)OUT_F * IN_F / 8];    // 86 MB
__device__ int   g_scale_mode;                      // 0=f32, 1=f16, 2=bf16

// ---------------- helpers ----------------
__device__ __forceinline__ uint32_t smem_u32(const void* p) {
    uint32_t a;
    asm("{ .reg .u64 t; cvta.to.shared.u64 t, %1; cvt.u32.u64 %0, t; }" : "=r"(a) : "l"(p));
    return a;
}
__device__ __forceinline__ uint32_t sw128(uint32_t off) {
    return off ^ ((off >> 3) & 0x70);
}
__device__ __forceinline__ void cp_async16(uint32_t dst, const void* src) {
    asm volatile("cp.async.cg.shared.global [%0], [%1], 16;" :: "r"(dst), "l"(src) : "memory");
}
__device__ __forceinline__ void cp_async_arrive_noinc(uint32_t mbar) {
    asm volatile("cp.async.mbarrier.arrive.noinc.shared.b64 [%0];" :: "r"(mbar) : "memory");
}
__device__ __forceinline__ void mbar_init(uint32_t mbar, uint32_t cnt) {
    asm volatile("mbarrier.init.shared.b64 [%0], %1;" :: "r"(mbar), "r"(cnt) : "memory");
}
__device__ __forceinline__ void mbar_arrive(uint32_t mbar) {
    asm volatile("mbarrier.arrive.shared.b64 _, [%0];" :: "r"(mbar) : "memory");
}
__device__ __forceinline__ void mbar_wait(uint32_t mbar, uint32_t parity) {
    asm volatile(
        "{\n\t.reg .pred P1;\n\t"
        "LAB_WAIT_%=:\n\t"
        "mbarrier.try_wait.parity.shared::cta.b64 P1, [%0], %1, 0x989680;\n\t"
        "@P1 bra LAB_DONE_%=;\n\t"
        "bra LAB_WAIT_%=;\n\t"
        "LAB_DONE_%=:\n\t}"
        :: "r"(mbar), "r"(parity) : "memory");
}
__device__ __forceinline__ void ldsm_x4(uint32_t* r, uint32_t addr) {
    asm volatile("ldmatrix.sync.aligned.m8n8.x4.shared.b16 {%0,%1,%2,%3}, [%4];"
                 : "=r"(r[0]), "=r"(r[1]), "=r"(r[2]), "=r"(r[3]) : "r"(addr));
}
__device__ __forceinline__ void mma16816(float* c, const uint32_t* a, const uint32_t* b) {
    asm("mma.sync.aligned.m16n8k16.row.col.f32.f16.f16.f32 "
        "{%0,%1,%2,%3}, {%4,%5,%6,%7}, {%8,%9}, {%0,%1,%2,%3};"
        : "+f"(c[0]), "+f"(c[1]), "+f"(c[2]), "+f"(c[3])
        : "r"(a[0]), "r"(a[1]), "r"(a[2]), "r"(a[3]), "r"(b[0]), "r"(b[1]));
}
__device__ __forceinline__ uint32_t h2_as_u32(__half2 h) {
    return *reinterpret_cast<uint32_t*>(&h);
}

// ---------------- scales dtype detection (parallel, 64 threads) ----------------
__global__ void detect_scale_kernel(const uint32_t* __restrict__ s) {
    int t = threadIdx.x;
    uint32_t w = s[t];
    float f = __uint_as_float(w);
    int f32ok = (f >= 1e-6f && f < 0.0101f) ? 1 : 0;
    int f16ok = 0, bf16ok = 0;
    uint32_t h[2] = { w & 0xFFFFu, w >> 16 };
    #pragma unroll
    for (int j = 0; j < 2; j++) {
        float fv = __half2float(__ushort_as_half((unsigned short)h[j]));
        if (fv >= 1e-6f && fv < 0.0101f) f16ok++;
        float bv = __uint_as_float(h[j] << 16);
        if (bv >= 1e-6f && bv < 0.0101f) bf16ok++;
    }
    __shared__ int cnt[3];
    if (t < 3) cnt[t] = 0;
    __syncthreads();
    atomicAdd(&cnt[0], f32ok);
    atomicAdd(&cnt[1], f16ok);
    atomicAdd(&cnt[2], bf16ok);
    __syncthreads();
    if (t == 0)
        g_scale_mode = (cnt[1] > 100) ? 1 : ((cnt[2] > 100) ? 2 : 0);
}

// ---------------- prep kernels ----------------
__global__ void prep_x_kernel(const float* __restrict__ x) {
    uint32_t idx = blockIdx.x * blockDim.x + threadIdx.x;     // 4194304 total
    uint32_t m = idx >> 9;
    uint32_t k = (idx & 511u) << 3;
    const float4* s = reinterpret_cast<const float4*>(x + (size_t)m * IN_F + k);
    float4 a = s[0], b = s[1];
    uint32_t u0 = h2_as_u32(__floats2half2_rn(a.x, a.y));
    uint32_t u1 = h2_as_u32(__floats2half2_rn(a.z, a.w));
    uint32_t u2 = h2_as_u32(__floats2half2_rn(b.x, b.y));
    uint32_t u3 = h2_as_u32(__floats2half2_rn(b.z, b.w));
    uint32_t mt = m >> 7, r = m & 127u, ks = k >> 6, c = k & 63u;
    size_t blk = ((size_t)mt * KSTAGES + ks) * TILE_BYTES;
    uint32_t off = sw128(r * 128 + c * 2);
    *reinterpret_cast<uint4*>(reinterpret_cast<char*>(g_x4) + blk + off) =
        make_uint4(u0, u1, u2, u3);
}

__global__ void prep_w_kernel(const int* __restrict__ q, const void* __restrict__ scales) {
    uint32_t idx = blockIdx.x * blockDim.x + threadIdx.x;     // 5636096 total
    uint32_t o = idx >> 9;
    uint32_t k = (idx & 511u) << 3;
    uint32_t sidx = o * (IN_F / GROUP) + (k >> 7);
    int mode = g_scale_mode;
    float sc;
    if (mode == 0)      sc = reinterpret_cast<const float*>(scales)[sidx];
    else if (mode == 1) sc = __half2float(reinterpret_cast<const __half*>(scales)[sidx]);
    else                sc = __uint_as_float(
                             (uint32_t)reinterpret_cast<const unsigned short*>(scales)[sidx] << 16);
    const int4* s = reinterpret_cast<const int4*>(q + (size_t)o * IN_F + k);
    int4 a = s[0], b = s[1];
    uint32_t u0 = h2_as_u32(__floats2half2_rn((float)a.x * sc, (float)a.y * sc));
    uint32_t u1 = h2_as_u32(__floats2half2_rn((float)a.z * sc, (float)a.w * sc));
    uint32_t u2 = h2_as_u32(__floats2half2_rn((float)b.x * sc, (float)b.y * sc));
    uint32_t u3 = h2_as_u32(__floats2half2_rn((float)b.z * sc, (float)b.w * sc));
    uint32_t nt = o >> 7, r = o & 127u, ks = k >> 6, c = k & 63u;
    size_t blk = ((size_t)nt * KSTAGES + ks) * TILE_BYTES;
    uint32_t off = sw128(r * 128 + c * 2);
    *reinterpret_cast<uint4*>(reinterpret_cast<char*>(g_w4) + blk + off) =
        make_uint4(u0, u1, u2, u3);
}

// ---------------- GEMM kernel (mma.sync + mbarrier pipeline) ----------------
// 256 threads, 8 warps: 2 (M) x 4 (N), warp tile 64x32. 2 CTAs/SM.
// No block-wide barriers in the mainloop: full[s] (count 256, cp.async arrivals)
// and empty[s] (count 8, one per warp) mbarriers decouple the warps.

__global__ __launch_bounds__(256, 2)
void gemm_kernel(float* __restrict__ out, const float* __restrict__ bias) {
    extern __shared__ __align__(1024) char smem[];
    uint32_t sb = smem_u32(smem);
    int tid = threadIdx.x;
    int lane = tid & 31, wid = tid >> 5;
    int warp_m = wid & 1, warp_n = wid >> 1;

    int bid = blockIdx.x;
    int group = bid / (GN * MT_TILES);
    int r_in  = bid % (GN * MT_TILES);
    int mt = r_in >> 1;                 // mt fastest inside group
    int nt = group * GN + (r_in & 1);

    const char* asrc = reinterpret_cast<const char*>(g_x4) + (size_t)mt * KSTAGES * TILE_BYTES;
    const char* bsrc = reinterpret_cast<const char*>(g_w4) + (size_t)nt * KSTAGES * TILE_BYTES;

    if (tid == 0) {
        #pragma unroll
        for (int s = 0; s < NSTAGES; s++) {
            mbar_init(sb + MB_FULL(s), 256);   // one cp.async-completion arrival per thread
            mbar_init(sb + MB_EMPTY(s), 8);    // one arrival per warp
        }
    }
    __syncthreads();   // barriers visible before first use (only block barrier)

    // produce: 8 x cp.async (16B) per thread + completion arrival on full[s]
    auto produce = [&](int s, int ks) {
        uint32_t dstbase = sb + s * STAGE_BYTES;
        if (tid < 128) {
            const char* src = asrc + (size_t)ks * TILE_BYTES + tid * 16;
            uint32_t dst = dstbase + tid * 16;
            #pragma unroll
            for (int j = 0; j < 8; j++) cp_async16(dst + j * 2048, src + j * 2048);
        } else {
            int t = tid - 128;
            const char* src = bsrc + (size_t)ks * TILE_BYTES + t * 16;
            uint32_t dst = dstbase + TILE_BYTES + t * 16;
            #pragma unroll
            for (int j = 0; j < 8; j++) cp_async16(dst + j * 2048, src + j * 2048);
        }
        cp_async_arrive_noinc(sb + MB_FULL(s));
    };

    float acc[4][4][4];
    #pragma unroll
    for (int i = 0; i < 4; i++)
        #pragma unroll
        for (int j = 0; j < 4; j++)
            #pragma unroll
            for (int v = 0; v < 4; v++) acc[i][j][v] = 0.0f;

    int a_row  = warp_m * 64 + (lane & 15);
    int a_kb   = (lane >> 4) << 4;
    int grp    = lane >> 3;
    int b_nrow = warp_n * 32 + ((grp >> 1) << 3) + (lane & 7);
    int b_kb   = (grp & 1) << 4;

    auto do_kk = [&](uint32_t Ab, uint32_t Bb, int kk) {
        uint32_t ra[4][4];
        uint32_t rb[4][2];
        int kbA = kk * 32 + a_kb;
        int kbB = kk * 32 + b_kb;
        ldsm_x4(ra[0], Ab + sw128((uint32_t)((a_row +  0) * 128 + kbA)));
        ldsm_x4(ra[1], Ab + sw128((uint32_t)((a_row + 16) * 128 + kbA)));
        {
            uint32_t r4[4];
            ldsm_x4(r4, Bb + sw128((uint32_t)((b_nrow + 0) * 128 + kbB)));
            rb[0][0] = r4[0]; rb[0][1] = r4[1];
            rb[1][0] = r4[2]; rb[1][1] = r4[3];
            ldsm_x4(r4, Bb + sw128((uint32_t)((b_nrow + 16) * 128 + kbB)));
            rb[2][0] = r4[0]; rb[2][1] = r4[1];
            rb[3][0] = r4[2]; rb[3][1] = r4[3];
        }
        #pragma unroll
        for (int in = 0; in < 4; in++) mma16816(acc[0][in], ra[0], rb[in]);
        ldsm_x4(ra[2], Ab + sw128((uint32_t)((a_row + 32) * 128 + kbA)));
        #pragma unroll
        for (int in = 0; in < 4; in++) mma16816(acc[1][in], ra[1], rb[in]);
        ldsm_x4(ra[3], Ab + sw128((uint32_t)((a_row + 48) * 128 + kbA)));
        #pragma unroll
        for (int in = 0; in < 4; in++) mma16816(acc[2][in], ra[2], rb[in]);
        #pragma unroll
        for (int in = 0; in < 4; in++) mma16816(acc[3][in], ra[3], rb[in]);
    };

    // Cursors. Producer empty-waits start parity 1 (pass immediately on fresh
    // barriers); consumer full-waits start parity 0.
    int pstage = 0, pph = 1;
    int cstage = 0, cph = 0;

    // prologue: produce stages 0,1 (empty-waits pass immediately)
    #pragma unroll
    for (int i = 0; i < NSTAGES - 1; i++) {
        mbar_wait(sb + MB_EMPTY(pstage), (uint32_t)pph);
        produce(pstage, i);
        if (++pstage == NSTAGES) { pstage = 0; pph ^= 1; }
    }

    for (int ks = 0; ks < KSTAGES; ks++) {
        mbar_wait(sb + MB_FULL(cstage), (uint32_t)cph);
        uint32_t Ab = sb + cstage * STAGE_BYTES;
        uint32_t Bb = Ab + TILE_BYTES;

        do_kk(Ab, Bb, 0);

        int ksn = ks + NSTAGES - 1;
        if (ksn < KSTAGES) {
            mbar_wait(sb + MB_EMPTY(pstage), (uint32_t)pph);
            produce(pstage, ksn);
            if (++pstage == NSTAGES) { pstage = 0; pph ^= 1; }
        }

        do_kk(Ab, Bb, 1);
        do_kk(Ab, Bb, 2);
        do_kk(Ab, Bb, 3);

        __syncwarp();
        if (lane == 0) mbar_arrive(sb + MB_EMPTY(cstage));
        if (++cstage == NSTAGES) { cstage = 0; cph ^= 1; }
    }

    // ---- epilogue: add bias, store float2 per c-frag pair ----
    #pragma unroll
    for (int im = 0; im < 4; im++) {
        int row = mt * BM + warp_m * 64 + im * 16 + (lane >> 2);
        #pragma unroll
        for (int in = 0; in < 4; in++) {
            int col = nt * BN + warp_n * 32 + in * 8 + ((lane & 3) << 1);
            float2 bv = *reinterpret_cast<const float2*>(bias + col);
            float2 v0 = make_float2(acc[im][in][0] + bv.x, acc[im][in][1] + bv.y);
            float2 v1 = make_float2(acc[im][in][2] + bv.x, acc[im][in][3] + bv.y);
            *reinterpret_cast<float2*>(out + (size_t)row * OUT_F + col) = v0;
            *reinterpret_cast<float2*>(out + (size_t)(row + 8) * OUT_F + col) = v1;
        }
    }
}

// ---------------- launch ----------------
extern "C" void kernel_launch(void* const* d_in, const int* in_sizes, int n_in,
                              void* d_out, int out_size) {
    const float* x    = nullptr;
    const int*   wq   = nullptr;
    const void*  sc   = nullptr;
    const float* bias = nullptr;
    for (int i = 0; i < n_in; i++) {
        long n = in_sizes[i];
        if      (n == (long)M_TOT * IN_F)           x    = (const float*)d_in[i];
        else if (n == (long)OUT_F * IN_F)           wq   = (const int*)d_in[i];
        else if (n == (long)OUT_F * (IN_F / GROUP)) sc   = d_in[i];
        else if (n == (long)OUT_F)                  bias = (const float*)d_in[i];
    }
    float* out = (float*)d_out;

    cudaFuncSetAttribute(gemm_kernel, cudaFuncAttributeMaxDynamicSharedMemorySize, SMEM_TOTAL);

    detect_scale_kernel<<<1, 64>>>((const uint32_t*)sc);
    prep_x_kernel<<<(M_TOT * IN_F / 8) / 256, 256>>>(x);
    prep_w_kernel<<<(OUT_F * IN_F / 8) / 256, 256>>>(wq, sc);

    gemm_kernel<<<NT_TILES * MT_TILES, 256, SMEM_TOTAL>>>(out, bias);
}

// round 10
// speedup vs baseline: 1.3792x; 1.0294x over previous
#include <cuda_runtime.h>
#include <cuda_fp16.h>
#include <cstdint>

// ---------------- problem constants ----------------
#define IN_F   4096
#define OUT_F  11008
#define M_TOT  8192
#define GROUP  128

// ---------------- GEMM tiling ----------------
#define BM 128
#define BN 128
#define BK 64                       // halves per k-stage (128B rows -> SW128 atom)
#define NSTAGES 3
#define MT_TILES (M_TOT / BM)       // 64
#define NT_TILES (OUT_F / BN)       // 86
#define KSTAGES  (IN_F / BK)        // 64
#define GN 2                        // nt columns per rasterization group

#define TILE_BYTES  (128 * BK * 2)            // 16384 per operand tile
#define STAGE_BYTES (2 * TILE_BYTES)          // 32768
#define MBAR_OFF    (NSTAGES * STAGE_BYTES)   // 98304
#define SMEM_TOTAL  (MBAR_OFF + 64)           // 98368 -> 2 CTAs/SM
#define MB_FULL(s)  (MBAR_OFF + (s) * 8)
#define MB_EMPTY(s) (MBAR_OFF + 24 + (s) * 8)

// ---------------- preprocessed operands (static device scratch) ----------------
__device__ uint4 g_x4[(size_t)M_TOT * IN_F / 8];    // 64 MB
__device__ uint4 g_w4[(size_t)OUT_F * IN_F / 8];    // 86 MB
__device__ int   g_scale_mode;                      // 0=f32, 1=f16, 2=bf16

// ---------------- helpers ----------------
__device__ __forceinline__ uint32_t smem_u32(const void* p) {
    uint32_t a;
    asm("{ .reg .u64 t; cvta.to.shared.u64 t, %1; cvt.u32.u64 %0, t; }" : "=r"(a) : "l"(p));
    return a;
}
__device__ __forceinline__ uint32_t sw128(uint32_t off) {
    return off ^ ((off >> 3) & 0x70);
}
__device__ __forceinline__ void cp_async16(uint32_t dst, const void* src) {
    asm volatile("cp.async.cg.shared.global [%0], [%1], 16;" :: "r"(dst), "l"(src) : "memory");
}
__device__ __forceinline__ void cp_async_arrive_noinc(uint32_t mbar) {
    asm volatile("cp.async.mbarrier.arrive.noinc.shared.b64 [%0];" :: "r"(mbar) : "memory");
}
__device__ __forceinline__ void mbar_init(uint32_t mbar, uint32_t cnt) {
    asm volatile("mbarrier.init.shared.b64 [%0], %1;" :: "r"(mbar), "r"(cnt) : "memory");
}
__device__ __forceinline__ void mbar_arrive(uint32_t mbar) {
    asm volatile("mbarrier.arrive.shared.b64 _, [%0];" :: "r"(mbar) : "memory");
}
__device__ __forceinline__ void mbar_wait(uint32_t mbar, uint32_t parity) {
    asm volatile(
        "{\n\t.reg .pred P1;\n\t"
        "LAB_WAIT_%=:\n\t"
        "mbarrier.try_wait.parity.shared::cta.b64 P1, [%0], %1, 0x989680;\n\t"
        "@P1 bra LAB_DONE_%=;\n\t"
        "bra LAB_WAIT_%=;\n\t"
        "LAB_DONE_%=:\n\t}"
        :: "r"(mbar), "r"(parity) : "memory");
}
__device__ __forceinline__ void ldsm_x4(uint32_t* r, uint32_t addr) {
    asm volatile("ldmatrix.sync.aligned.m8n8.x4.shared.b16 {%0,%1,%2,%3}, [%4];"
                 : "=r"(r[0]), "=r"(r[1]), "=r"(r[2]), "=r"(r[3]) : "r"(addr));
}
__device__ __forceinline__ void mma16816(float* c, const uint32_t* a, const uint32_t* b) {
    asm("mma.sync.aligned.m16n8k16.row.col.f32.f16.f16.f32 "
        "{%0,%1,%2,%3}, {%4,%5,%6,%7}, {%8,%9}, {%0,%1,%2,%3};"
        : "+f"(c[0]), "+f"(c[1]), "+f"(c[2]), "+f"(c[3])
        : "r"(a[0]), "r"(a[1]), "r"(a[2]), "r"(a[3]), "r"(b[0]), "r"(b[1]));
}
__device__ __forceinline__ uint32_t h2_as_u32(__half2 h) {
    return *reinterpret_cast<uint32_t*>(&h);
}

// ---------------- scales dtype detection (parallel, 64 threads) ----------------
__global__ void detect_scale_kernel(const uint32_t* __restrict__ s) {
    int t = threadIdx.x;
    uint32_t w = s[t];
    float f = __uint_as_float(w);
    int f32ok = (f >= 1e-6f && f < 0.0101f) ? 1 : 0;
    int f16ok = 0, bf16ok = 0;
    uint32_t h[2] = { w & 0xFFFFu, w >> 16 };
    #pragma unroll
    for (int j = 0; j < 2; j++) {
        float fv = __half2float(__ushort_as_half((unsigned short)h[j]));
        if (fv >= 1e-6f && fv < 0.0101f) f16ok++;
        float bv = __uint_as_float(h[j] << 16);
        if (bv >= 1e-6f && bv < 0.0101f) bf16ok++;
    }
    __shared__ int cnt[3];
    if (t < 3) cnt[t] = 0;
    __syncthreads();
    atomicAdd(&cnt[0], f32ok);
    atomicAdd(&cnt[1], f16ok);
    atomicAdd(&cnt[2], bf16ok);
    __syncthreads();
    if (t == 0)
        g_scale_mode = (cnt[1] > 100) ? 1 : ((cnt[2] > 100) ? 2 : 0);
}

// ---------------- prep kernels ----------------
__global__ void prep_x_kernel(const float* __restrict__ x) {
    uint32_t idx = blockIdx.x * blockDim.x + threadIdx.x;     // 4194304 total
    uint32_t m = idx >> 9;
    uint32_t k = (idx & 511u) << 3;
    const float4* s = reinterpret_cast<const float4*>(x + (size_t)m * IN_F + k);
    float4 a = s[0], b = s[1];
    uint32_t u0 = h2_as_u32(__floats2half2_rn(a.x, a.y));
    uint32_t u1 = h2_as_u32(__floats2half2_rn(a.z, a.w));
    uint32_t u2 = h2_as_u32(__floats2half2_rn(b.x, b.y));
    uint32_t u3 = h2_as_u32(__floats2half2_rn(b.z, b.w));
    uint32_t mt = m >> 7, r = m & 127u, ks = k >> 6, c = k & 63u;
    size_t blk = ((size_t)mt * KSTAGES + ks) * TILE_BYTES;
    uint32_t off = sw128(r * 128 + c * 2);
    *reinterpret_cast<uint4*>(reinterpret_cast<char*>(g_x4) + blk + off) =
        make_uint4(u0, u1, u2, u3);
}

__global__ void prep_w_kernel(const int* __restrict__ q, const void* __restrict__ scales) {
    uint32_t idx = blockIdx.x * blockDim.x + threadIdx.x;     // 5636096 total
    uint32_t o = idx >> 9;
    uint32_t k = (idx & 511u) << 3;
    uint32_t sidx = o * (IN_F / GROUP) + (k >> 7);
    int mode = g_scale_mode;
    float sc;
    if (mode == 0)      sc = reinterpret_cast<const float*>(scales)[sidx];
    else if (mode == 1) sc = __half2float(reinterpret_cast<const __half*>(scales)[sidx]);
    else                sc = __uint_as_float(
                             (uint32_t)reinterpret_cast<const unsigned short*>(scales)[sidx] << 16);
    const int4* s = reinterpret_cast<const int4*>(q + (size_t)o * IN_F + k);
    int4 a = s[0], b = s[1];
    uint32_t u0 = h2_as_u32(__floats2half2_rn((float)a.x * sc, (float)a.y * sc));
    uint32_t u1 = h2_as_u32(__floats2half2_rn((float)a.z * sc, (float)a.w * sc));
    uint32_t u2 = h2_as_u32(__floats2half2_rn((float)b.x * sc, (float)b.y * sc));
    uint32_t u3 = h2_as_u32(__floats2half2_rn((float)b.z * sc, (float)b.w * sc));
    uint32_t nt = o >> 7, r = o & 127u, ks = k >> 6, c = k & 63u;
    size_t blk = ((size_t)nt * KSTAGES + ks) * TILE_BYTES;
    uint32_t off = sw128(r * 128 + c * 2);
    *reinterpret_cast<uint4*>(reinterpret_cast<char*>(g_w4) + blk + off) =
        make_uint4(u0, u1, u2, u3);
}

// ---------------- GEMM kernel (mma.sync + mbarrier pipeline) ----------------
// 128 threads, 4 warps in 2(M) x 2(N), warp tile 64x64. 2 CTAs/SM.
// Cuts smem read traffic: A read 2x + B read 2x = 64KB/stage (vs 96KB with
// 8 warps of 64x32) -> smem crossbar no longer the binder.

__global__ __launch_bounds__(128, 2)
void gemm_kernel(float* __restrict__ out, const float* __restrict__ bias) {
    extern __shared__ __align__(1024) char smem[];
    uint32_t sb = smem_u32(smem);
    int tid = threadIdx.x;
    int lane = tid & 31, wid = tid >> 5;
    int warp_m = wid & 1, warp_n = wid >> 1;        // 2 x 2

    int bid = blockIdx.x;
    int group = bid / (GN * MT_TILES);
    int r_in  = bid % (GN * MT_TILES);
    int mt = r_in >> 1;                 // mt fastest inside group
    int nt = group * GN + (r_in & 1);

    const char* asrc = reinterpret_cast<const char*>(g_x4) + (size_t)mt * KSTAGES * TILE_BYTES;
    const char* bsrc = reinterpret_cast<const char*>(g_w4) + (size_t)nt * KSTAGES * TILE_BYTES;

    if (tid == 0) {
        #pragma unroll
        for (int s = 0; s < NSTAGES; s++) {
            mbar_init(sb + MB_FULL(s), 128);   // one cp.async arrival per thread
            mbar_init(sb + MB_EMPTY(s), 4);    // one arrival per warp
        }
    }
    __syncthreads();

    // produce: 16 x cp.async (16B) per thread + completion arrival on full[s]
    auto produce = [&](int s, int ks) {
        uint32_t dstbase = sb + s * STAGE_BYTES;
        if (tid < 64) {
            const char* src = asrc + (size_t)ks * TILE_BYTES + tid * 16;
            uint32_t dst = dstbase + tid * 16;
            #pragma unroll
            for (int j = 0; j < 16; j++) cp_async16(dst + j * 1024, src + j * 1024);
        } else {
            int t = tid - 64;
            const char* src = bsrc + (size_t)ks * TILE_BYTES + t * 16;
            uint32_t dst = dstbase + TILE_BYTES + t * 16;
            #pragma unroll
            for (int j = 0; j < 16; j++) cp_async16(dst + j * 1024, src + j * 1024);
        }
        cp_async_arrive_noinc(sb + MB_FULL(s));
    };

    float acc[4][8][4];
    #pragma unroll
    for (int i = 0; i < 4; i++)
        #pragma unroll
        for (int j = 0; j < 8; j++)
            #pragma unroll
            for (int v = 0; v < 4; v++) acc[i][j][v] = 0.0f;

    int a_row  = warp_m * 64 + (lane & 15);
    int a_kb   = (lane >> 4) << 4;
    int grp    = lane >> 3;
    int b_nrow = warp_n * 64 + ((grp >> 1) << 3) + (lane & 7);   // + ib*16
    int b_kb   = (grp & 1) << 4;

    auto do_kk = [&](uint32_t Ab, uint32_t Bb, int kk) {
        uint32_t ra[4][4];
        uint32_t rb[8][2];
        int kbA = kk * 32 + a_kb;
        int kbB = kk * 32 + b_kb;
        ldsm_x4(ra[0], Ab + sw128((uint32_t)((a_row +  0) * 128 + kbA)));
        ldsm_x4(ra[1], Ab + sw128((uint32_t)((a_row + 16) * 128 + kbA)));
        #pragma unroll
        for (int ib = 0; ib < 4; ib++) {
            uint32_t r4[4];
            ldsm_x4(r4, Bb + sw128((uint32_t)((b_nrow + ib * 16) * 128 + kbB)));
            rb[ib * 2 + 0][0] = r4[0]; rb[ib * 2 + 0][1] = r4[1];
            rb[ib * 2 + 1][0] = r4[2]; rb[ib * 2 + 1][1] = r4[3];
        }
        #pragma unroll
        for (int in = 0; in < 8; in++) mma16816(acc[0][in], ra[0], rb[in]);
        ldsm_x4(ra[2], Ab + sw128((uint32_t)((a_row + 32) * 128 + kbA)));
        #pragma unroll
        for (int in = 0; in < 8; in++) mma16816(acc[1][in], ra[1], rb[in]);
        ldsm_x4(ra[3], Ab + sw128((uint32_t)((a_row + 48) * 128 + kbA)));
        #pragma unroll
        for (int in = 0; in < 8; in++) mma16816(acc[2][in], ra[2], rb[in]);
        #pragma unroll
        for (int in = 0; in < 8; in++) mma16816(acc[3][in], ra[3], rb[in]);
    };

    int pstage = 0, pph = 1;
    int cstage = 0, cph = 0;

    #pragma unroll
    for (int i = 0; i < NSTAGES - 1; i++) {
        mbar_wait(sb + MB_EMPTY(pstage), (uint32_t)pph);
        produce(pstage, i);
        if (++pstage == NSTAGES) { pstage = 0; pph ^= 1; }
    }

    for (int ks = 0; ks < KSTAGES; ks++) {
        mbar_wait(sb + MB_FULL(cstage), (uint32_t)cph);
        uint32_t Ab = sb + cstage * STAGE_BYTES;
        uint32_t Bb = Ab + TILE_BYTES;

        do_kk(Ab, Bb, 0);

        int ksn = ks + NSTAGES - 1;
        if (ksn < KSTAGES) {
            mbar_wait(sb + MB_EMPTY(pstage), (uint32_t)pph);
            produce(pstage, ksn);
            if (++pstage == NSTAGES) { pstage = 0; pph ^= 1; }
        }

        do_kk(Ab, Bb, 1);
        do_kk(Ab, Bb, 2);
        do_kk(Ab, Bb, 3);

        __syncwarp();
        if (lane == 0) mbar_arrive(sb + MB_EMPTY(cstage));
        if (++cstage == NSTAGES) { cstage = 0; cph ^= 1; }
    }

    // ---- epilogue: add bias (hoisted loads), store float2 per c-frag pair ----
    float2 bv[8];
    #pragma unroll
    for (int in = 0; in < 8; in++) {
        int col = nt * BN + warp_n * 64 + in * 8 + ((lane & 3) << 1);
        bv[in] = *reinterpret_cast<const float2*>(bias + col);
    }
    #pragma unroll
    for (int im = 0; im < 4; im++) {
        int row = mt * BM + warp_m * 64 + im * 16 + (lane >> 2);
        #pragma unroll
        for (int in = 0; in < 8; in++) {
            int col = nt * BN + warp_n * 64 + in * 8 + ((lane & 3) << 1);
            float2 v0 = make_float2(acc[im][in][0] + bv[in].x, acc[im][in][1] + bv[in].y);
            float2 v1 = make_float2(acc[im][in][2] + bv[in].x, acc[im][in][3] + bv[in].y);
            *reinterpret_cast<float2*>(out + (size_t)row * OUT_F + col) = v0;
            *reinterpret_cast<float2*>(out + (size_t)(row + 8) * OUT_F + col) = v1;
        }
    }
}

// ---------------- launch ----------------
extern "C" void kernel_launch(void* const* d_in, const int* in_sizes, int n_in,
                              void* d_out, int out_size) {
    const float* x    = nullptr;
    const int*   wq   = nullptr;
    const void*  sc   = nullptr;
    const float* bias = nullptr;
    for (int i = 0; i < n_in; i++) {
        long n = in_sizes[i];
        if      (n == (long)M_TOT * IN_F)           x    = (const float*)d_in[i];
        else if (n == (long)OUT_F * IN_F)           wq   = (const int*)d_in[i];
        else if (n == (long)OUT_F * (IN_F / GROUP)) sc   = d_in[i];
        else if (n == (long)OUT_F)                  bias = (const float*)d_in[i];
    }
    float* out = (float*)d_out;

    cudaFuncSetAttribute(gemm_kernel, cudaFuncAttributeMaxDynamicSharedMemorySize, SMEM_TOTAL);

    detect_scale_kernel<<<1, 64>>>((const uint32_t*)sc);
    prep_x_kernel<<<(M_TOT * IN_F / 8) / 256, 256>>>(x);
    prep_w_kernel<<<(OUT_F * IN_F / 8) / 256, 256>>>(wq, sc);

    gemm_kernel<<<NT_TILES * MT_TILES, 128, SMEM_TOTAL>>>(out, bias);
}